// round 1
// baseline (speedup 1.0000x reference)
#include <cuda_runtime.h>
#include <math_constants.h>

#define Dq 1024
#define Bq 16
#define BM 128
#define BN 128
#define BKq 8
#define TM 8
#define TN 8

// Scratch (allocation-free rule: __device__ globals)
__device__ float g_T[(size_t)Bq * Dq * Dq];   // T[b] = W @ E[b], 64 MB
__device__ float g_rowmax[Bq * Dq];

__device__ __forceinline__ void atomicMaxF(float* addr, float val) {
    int old = __float_as_int(*addr);
    while (__int_as_float(old) < val) {
        int assumed = old;
        old = atomicCAS((int*)addr, assumed, __float_as_int(val));
        if (old == assumed) break;
    }
}

__global__ void init_rowmax_k() {
    int i = blockIdx.x * blockDim.x + threadIdx.x;
    if (i < Bq * Dq) g_rowmax[i] = -CUDART_INF_F;
}

// ---------------------------------------------------------------------------
// Kernel 1: T[b] = W (D x D, row-major) @ E[b] (D x D, row-major)
// Block tile 128x128, K-tile 8, 256 threads, 8x8 microtile per thread.
// ---------------------------------------------------------------------------
__global__ __launch_bounds__(256) void gemm1_k(const float* __restrict__ W,
                                               const float* __restrict__ E) {
    __shared__ float As[BKq][BM];   // transposed A tile
    __shared__ float Bs[BKq][BN];

    const int b = blockIdx.z;
    const float* __restrict__ Eb = E + (size_t)b * Dq * Dq;
    float* __restrict__ Cb = g_T + (size_t)b * Dq * Dq;

    const int rowBase = blockIdx.y * BM;
    const int colBase = blockIdx.x * BN;
    const int t  = threadIdx.x;
    const int tx = t & 15;         // 0..15 -> N direction
    const int ty = t >> 4;         // 0..15 -> M direction

    float acc[TM][TN];
#pragma unroll
    for (int i = 0; i < TM; i++)
#pragma unroll
        for (int j = 0; j < TN; j++) acc[i][j] = 0.f;

    const int aRow = t >> 1;         // 0..127
    const int aK   = (t & 1) * 4;    // 0 or 4
    const int bRow = t >> 5;         // 0..7
    const int bCol = (t & 31) * 4;   // 0..124

    for (int k0 = 0; k0 < Dq; k0 += BKq) {
        float4 av = *(const float4*)(&W[(size_t)(rowBase + aRow) * Dq + k0 + aK]);
        As[aK + 0][aRow] = av.x;
        As[aK + 1][aRow] = av.y;
        As[aK + 2][aRow] = av.z;
        As[aK + 3][aRow] = av.w;
        *(float4*)(&Bs[bRow][bCol]) =
            *(const float4*)(&Eb[(size_t)(k0 + bRow) * Dq + colBase + bCol]);
        __syncthreads();

#pragma unroll
        for (int k = 0; k < BKq; k++) {
            float rm[TM], rn[TN];
#pragma unroll
            for (int i = 0; i < TM; i++) rm[i] = As[k][ty * TM + i];
#pragma unroll
            for (int j = 0; j < TN; j++) rn[j] = Bs[k][tx * TN + j];
#pragma unroll
            for (int i = 0; i < TM; i++)
#pragma unroll
                for (int j = 0; j < TN; j++)
                    acc[i][j] = fmaf(rm[i], rn[j], acc[i][j]);
        }
        __syncthreads();
    }

#pragma unroll
    for (int i = 0; i < TM; i++) {
        int r = rowBase + ty * TM + i;
        float* dst = &Cb[(size_t)r * Dq + colBase + tx * TN];
        *(float4*)(dst + 0) = make_float4(acc[i][0], acc[i][1], acc[i][2], acc[i][3]);
        *(float4*)(dst + 4) = make_float4(acc[i][4], acc[i][5], acc[i][6], acc[i][7]);
    }
}

// ---------------------------------------------------------------------------
// Kernel 2: S = E[b]^T @ T[b], fused row-max (never materialize S).
// A[m][k] = E[k][m]  (contiguous along m -> direct float4 loads, no transpose)
// ---------------------------------------------------------------------------
__global__ __launch_bounds__(256) void gemm2_max_k(const float* __restrict__ E) {
    __shared__ float As[BKq][BM];
    __shared__ float Bs[BKq][BN];
    __shared__ float red[BM][17];   // padded to kill bank conflicts

    const int b = blockIdx.z;
    const float* __restrict__ Eb = E + (size_t)b * Dq * Dq;
    const float* __restrict__ Tb = g_T + (size_t)b * Dq * Dq;

    const int rowBase = blockIdx.y * BM;   // n1
    const int colBase = blockIdx.x * BN;   // n2
    const int t  = threadIdx.x;
    const int tx = t & 15;
    const int ty = t >> 4;

    float acc[TM][TN];
#pragma unroll
    for (int i = 0; i < TM; i++)
#pragma unroll
        for (int j = 0; j < TN; j++) acc[i][j] = 0.f;

    const int ldRow = t >> 5;         // 0..7  (k within tile)
    const int ldCol = (t & 31) * 4;   // 0..124

    for (int k0 = 0; k0 < Dq; k0 += BKq) {
        // A tile: As[k][m] = E[k0+k][rowBase+m]   (contiguous in m)
        *(float4*)(&As[ldRow][ldCol]) =
            *(const float4*)(&Eb[(size_t)(k0 + ldRow) * Dq + rowBase + ldCol]);
        // B tile: Bs[k][n] = T[k0+k][colBase+n]
        *(float4*)(&Bs[ldRow][ldCol]) =
            *(const float4*)(&Tb[(size_t)(k0 + ldRow) * Dq + colBase + ldCol]);
        __syncthreads();

#pragma unroll
        for (int k = 0; k < BKq; k++) {
            float rm[TM], rn[TN];
#pragma unroll
            for (int i = 0; i < TM; i++) rm[i] = As[k][ty * TM + i];
#pragma unroll
            for (int j = 0; j < TN; j++) rn[j] = Bs[k][tx * TN + j];
#pragma unroll
            for (int i = 0; i < TM; i++)
#pragma unroll
                for (int j = 0; j < TN; j++)
                    acc[i][j] = fmaf(rm[i], rn[j], acc[i][j]);
        }
        __syncthreads();
    }

    // per-thread row max over its 8 columns
#pragma unroll
    for (int i = 0; i < TM; i++) {
        float m = acc[i][0];
#pragma unroll
        for (int j = 1; j < TN; j++) m = fmaxf(m, acc[i][j]);
        red[ty * TM + i][tx] = m;
    }
    __syncthreads();

    if (t < BM) {
        float m = red[t][0];
#pragma unroll
        for (int j = 1; j < 16; j++) m = fmaxf(m, red[t][j]);
        atomicMaxF(&g_rowmax[b * Dq + rowBase + t], m);
    }
}

// ---------------------------------------------------------------------------
// Kernel 3: out[b, n] = softmax_n( tanh(rowmax[b, n]) )
// ---------------------------------------------------------------------------
__global__ __launch_bounds__(1024) void softmax_k(float* __restrict__ out) {
    const int b = blockIdx.x;
    const int t = threadIdx.x;
    __shared__ float smax[32];
    __shared__ float ssum[32];

    float v = tanhf(g_rowmax[b * Dq + t]);

    // block max
    float m = v;
#pragma unroll
    for (int o = 16; o > 0; o >>= 1) m = fmaxf(m, __shfl_xor_sync(0xffffffffu, m, o));
    if ((t & 31) == 0) smax[t >> 5] = m;
    __syncthreads();
    if (t < 32) {
        float x = smax[t];
#pragma unroll
        for (int o = 16; o > 0; o >>= 1) x = fmaxf(x, __shfl_xor_sync(0xffffffffu, x, o));
        smax[t] = x;
    }
    __syncthreads();
    const float M = smax[0];

    float e = expf(v - M);

    // block sum
    float s = e;
#pragma unroll
    for (int o = 16; o > 0; o >>= 1) s += __shfl_xor_sync(0xffffffffu, s, o);
    if ((t & 31) == 0) ssum[t >> 5] = s;
    __syncthreads();
    if (t < 32) {
        float x = ssum[t];
#pragma unroll
        for (int o = 16; o > 0; o >>= 1) x += __shfl_xor_sync(0xffffffffu, x, o);
        ssum[t] = x;
    }
    __syncthreads();
    const float S = ssum[0];

    out[b * Dq + t] = e / S;
}

// ---------------------------------------------------------------------------
extern "C" void kernel_launch(void* const* d_in, const int* in_sizes, int n_in,
                              void* d_out, int out_size) {
    const float* emb = (const float*)d_in[0];   // [B, D, N]
    // d_in[1] = heatm (unused by forward)
    const float* W   = (const float*)d_in[2];   // [D, D]
    float* out = (float*)d_out;                 // [B, N, 1]

    init_rowmax_k<<<(Bq * Dq + 1023) / 1024, 1024>>>();

    dim3 grid(Dq / BN, Dq / BM, Bq);   // (8, 8, 16)
    gemm1_k<<<grid, 256>>>(W, emb);
    gemm2_max_k<<<grid, 256>>>(emb);
    softmax_k<<<Bq, 1024>>>(out);
}

// round 2
// speedup vs baseline: 3.9915x; 3.9915x over previous
#include <cuda_runtime.h>
#include <cuda_bf16.h>
#include <math_constants.h>
#include <cstdint>

#define Dq 1024
#define Bq 16

#define BM 128
#define BN 128
#define BK 32
#define PAD 8
#define ASTRIDE (BK + PAD)    // 40 elems -> 80B row stride (conflict-free for ldmatrix)
#define BSTRIDE (BN + PAD)    // 136 elems -> 272B row stride

// ---- scratch (__device__ globals: allocation-free rule) --------------------
__device__ __nv_bfloat16 g_Wh[(size_t)Dq * Dq];            // 2 MB
__device__ __nv_bfloat16 g_Eh[(size_t)Bq * Dq * Dq];       // 32 MB  E  [b][d][n]
__device__ __nv_bfloat16 g_ETh[(size_t)Bq * Dq * Dq];      // 32 MB  E^T[b][n][d]
__device__ __nv_bfloat16 g_Th[(size_t)Bq * Dq * Dq];       // 32 MB  T = W@E
__device__ float g_rowmax[Bq * Dq];

// ---- small helpers ---------------------------------------------------------
__device__ __forceinline__ void atomicMaxF(float* addr, float val) {
    int old = __float_as_int(*addr);
    while (__int_as_float(old) < val) {
        int assumed = old;
        old = atomicCAS((int*)addr, assumed, __float_as_int(val));
        if (old == assumed) break;
    }
}

__device__ __forceinline__ void cp16(uint32_t s, const void* g) {
    asm volatile("cp.async.cg.shared.global [%0], [%1], 16;\n" :: "r"(s), "l"(g));
}
__device__ __forceinline__ void cp_commit() { asm volatile("cp.async.commit_group;\n"); }
template <int N>
__device__ __forceinline__ void cp_wait() { asm volatile("cp.async.wait_group %0;\n" :: "n"(N)); }

__device__ __forceinline__ void ldsm4(uint32_t* r, uint32_t addr) {
    asm volatile("ldmatrix.sync.aligned.m8n8.x4.shared.b16 {%0,%1,%2,%3}, [%4];"
                 : "=r"(r[0]), "=r"(r[1]), "=r"(r[2]), "=r"(r[3]) : "r"(addr));
}
__device__ __forceinline__ void ldsm4t(uint32_t* r, uint32_t addr) {
    asm volatile("ldmatrix.sync.aligned.m8n8.x4.trans.shared.b16 {%0,%1,%2,%3}, [%4];"
                 : "=r"(r[0]), "=r"(r[1]), "=r"(r[2]), "=r"(r[3]) : "r"(addr));
}
__device__ __forceinline__ void mma_bf16(float* d, const uint32_t* a, uint32_t b0, uint32_t b1) {
    asm volatile("mma.sync.aligned.m16n8k16.row.col.f32.bf16.bf16.f32 "
                 "{%0,%1,%2,%3}, {%4,%5,%6,%7}, {%8,%9}, {%0,%1,%2,%3};"
                 : "+f"(d[0]), "+f"(d[1]), "+f"(d[2]), "+f"(d[3])
                 : "r"(a[0]), "r"(a[1]), "r"(a[2]), "r"(a[3]), "r"(b0), "r"(b1));
}

// ---- setup kernels ---------------------------------------------------------
__global__ void init_rowmax_k() {
    int i = blockIdx.x * blockDim.x + threadIdx.x;
    if (i < Bq * Dq) g_rowmax[i] = -CUDART_INF_F;
}

__global__ void convert_W_k(const float* __restrict__ W) {
    int i = blockIdx.x * 256 + threadIdx.x;
    g_Wh[i] = __float2bfloat16(W[i]);
}

// E [b][d][n] fp32 -> g_Eh (same layout, bf16) and g_ETh ([b][n][d], bf16)
__global__ void convert_E_k(const float* __restrict__ E) {
    __shared__ float tile[32][33];
    const int b = blockIdx.z;
    const int x0 = blockIdx.x * 32, y0 = blockIdx.y * 32;
    const float* __restrict__ Eb = E + (size_t)b * Dq * Dq;
    const int tx = threadIdx.x, ty = threadIdx.y;   // 32 x 8
#pragma unroll
    for (int i = 0; i < 4; i++) {
        int y = ty + i * 8;
        float v = Eb[(size_t)(y0 + y) * Dq + x0 + tx];
        tile[y][tx] = v;
        g_Eh[(size_t)b * Dq * Dq + (size_t)(y0 + y) * Dq + x0 + tx] = __float2bfloat16(v);
    }
    __syncthreads();
#pragma unroll
    for (int i = 0; i < 4; i++) {
        int y = ty + i * 8;
        g_ETh[(size_t)b * Dq * Dq + (size_t)(x0 + y) * Dq + y0 + tx] =
            __float2bfloat16(tile[tx][y]);
    }
}

// ---- tensor-core GEMM (both stages) ----------------------------------------
// GEMM1 = true : C = W @ E[b]              -> g_Th[b] (bf16)
// GEMM1 = false: S = E^T[b] @ T[b], fused rowmax -> g_rowmax
template <bool GEMM1>
__global__ __launch_bounds__(256) void mma_gemm_k() {
    __shared__ __nv_bfloat16 As[2][BM * ASTRIDE];   // 2 * 10240 B
    __shared__ __nv_bfloat16 Bs[2][BK * BSTRIDE];   // 2 *  8704 B

    const int b = blockIdx.z;
    const int rowBase = blockIdx.y * BM;
    const int colBase = blockIdx.x * BN;

    const __nv_bfloat16* __restrict__ A =
        GEMM1 ? g_Wh : (g_ETh + (size_t)b * Dq * Dq);
    const __nv_bfloat16* __restrict__ B =
        (GEMM1 ? g_Eh : g_Th) + (size_t)b * Dq * Dq;

    const int t = threadIdx.x;
    const int lane = t & 31;
    const int wid = t >> 5;
    const int wm = wid >> 1;      // 0..3  (M direction, 32 rows each)
    const int wn = wid & 1;       // 0..1  (N direction, 64 cols each)

    const uint32_t sA = (uint32_t)__cvta_generic_to_shared(&As[0][0]);
    const uint32_t sB = (uint32_t)__cvta_generic_to_shared(&Bs[0][0]);

    // global->shared load coordinates (16B per cp.async)
    const int aR0 = t >> 2, aC = (t & 3) * 8;          // +2nd chunk at t+256
    const int bR0 = t >> 4, bC = (t & 15) * 8;

    float acc[2][8][4];
#pragma unroll
    for (int mi = 0; mi < 2; mi++)
#pragma unroll
        for (int ni = 0; ni < 8; ni++)
#pragma unroll
            for (int r = 0; r < 4; r++) acc[mi][ni][r] = 0.f;

    auto load_stage = [&](int buf, int k0) {
        uint32_t dA = sA + (uint32_t)(buf * BM * ASTRIDE) * 2;
        uint32_t dB = sB + (uint32_t)(buf * BK * BSTRIDE) * 2;
#pragma unroll
        for (int i = 0; i < 2; i++) {
            int idx = t + i * 256;
            int r = idx >> 2, c = (idx & 3) * 8;
            cp16(dA + (uint32_t)(r * ASTRIDE + c) * 2,
                 A + (size_t)(rowBase + r) * Dq + k0 + c);
        }
#pragma unroll
        for (int i = 0; i < 2; i++) {
            int idx = t + i * 256;
            int r = idx >> 4, c = (idx & 15) * 8;
            cp16(dB + (uint32_t)(r * BSTRIDE + c) * 2,
                 B + (size_t)(k0 + r) * Dq + colBase + c);
        }
        cp_commit();
    };

    auto compute_stage = [&](int buf) {
        uint32_t bA = sA + (uint32_t)(buf * BM * ASTRIDE) * 2;
        uint32_t bB = sB + (uint32_t)(buf * BK * BSTRIDE) * 2;
#pragma unroll
        for (int ki = 0; ki < 2; ki++) {
            uint32_t afr[2][4];
#pragma unroll
            for (int mi = 0; mi < 2; mi++) {
                int row = wm * 32 + mi * 16 + (lane & 15);
                int col = ki * 16 + (lane >> 4) * 8;
                ldsm4(afr[mi], bA + (uint32_t)(row * ASTRIDE + col) * 2);
            }
            uint32_t bfr[4][4];
#pragma unroll
            for (int np = 0; np < 4; np++) {
                int q = lane >> 3, r = lane & 7;
                int krow = ki * 16 + (q & 1) * 8 + r;
                int ncol = wn * 64 + np * 16 + (q >> 1) * 8;
                ldsm4t(bfr[np], bB + (uint32_t)(krow * BSTRIDE + ncol) * 2);
            }
#pragma unroll
            for (int mi = 0; mi < 2; mi++)
#pragma unroll
                for (int np = 0; np < 4; np++) {
                    mma_bf16(acc[mi][2 * np + 0], afr[mi], bfr[np][0], bfr[np][1]);
                    mma_bf16(acc[mi][2 * np + 1], afr[mi], bfr[np][2], bfr[np][3]);
                }
        }
    };

    const int kTiles = Dq / BK;   // 32
    load_stage(0, 0);
    for (int kt = 0; kt < kTiles; kt++) {
        if (kt + 1 < kTiles) {
            load_stage((kt + 1) & 1, (kt + 1) * BK);
            cp_wait<1>();
        } else {
            cp_wait<0>();
        }
        __syncthreads();
        compute_stage(kt & 1);
        __syncthreads();
    }

    const int g = lane >> 2, q4 = lane & 3;
    if (GEMM1) {
        __nv_bfloat16* __restrict__ Tb = g_Th + (size_t)b * Dq * Dq;
#pragma unroll
        for (int mi = 0; mi < 2; mi++) {
            int row0 = rowBase + wm * 32 + mi * 16 + g;
#pragma unroll
            for (int ni = 0; ni < 8; ni++) {
                int col = colBase + wn * 64 + ni * 8 + q4 * 2;
                __nv_bfloat162 v01, v23;
                v01.x = __float2bfloat16(acc[mi][ni][0]);
                v01.y = __float2bfloat16(acc[mi][ni][1]);
                v23.x = __float2bfloat16(acc[mi][ni][2]);
                v23.y = __float2bfloat16(acc[mi][ni][3]);
                *(__nv_bfloat162*)(Tb + (size_t)row0 * Dq + col) = v01;
                *(__nv_bfloat162*)(Tb + (size_t)(row0 + 8) * Dq + col) = v23;
            }
        }
    } else {
#pragma unroll
        for (int mi = 0; mi < 2; mi++) {
            float m0 = -CUDART_INF_F, m1 = -CUDART_INF_F;
#pragma unroll
            for (int ni = 0; ni < 8; ni++) {
                m0 = fmaxf(m0, fmaxf(acc[mi][ni][0], acc[mi][ni][1]));
                m1 = fmaxf(m1, fmaxf(acc[mi][ni][2], acc[mi][ni][3]));
            }
            // reduce across the 4 lanes sharing a row (lane&3 varies over n)
            m0 = fmaxf(m0, __shfl_xor_sync(0xffffffffu, m0, 1));
            m0 = fmaxf(m0, __shfl_xor_sync(0xffffffffu, m0, 2));
            m1 = fmaxf(m1, __shfl_xor_sync(0xffffffffu, m1, 1));
            m1 = fmaxf(m1, __shfl_xor_sync(0xffffffffu, m1, 2));
            if (q4 == 0) {
                int row = rowBase + wm * 32 + mi * 16 + g;
                atomicMaxF(&g_rowmax[b * Dq + row], m0);
                atomicMaxF(&g_rowmax[b * Dq + row + 8], m1);
            }
        }
    }
}

// ---- softmax over tanh(rowmax) ---------------------------------------------
__global__ __launch_bounds__(1024) void softmax_k(float* __restrict__ out) {
    const int b = blockIdx.x;
    const int t = threadIdx.x;
    __shared__ float smax[32];
    __shared__ float ssum[32];

    float v = tanhf(g_rowmax[b * Dq + t]);

    float m = v;
#pragma unroll
    for (int o = 16; o > 0; o >>= 1) m = fmaxf(m, __shfl_xor_sync(0xffffffffu, m, o));
    if ((t & 31) == 0) smax[t >> 5] = m;
    __syncthreads();
    if (t < 32) {
        float x = smax[t];
#pragma unroll
        for (int o = 16; o > 0; o >>= 1) x = fmaxf(x, __shfl_xor_sync(0xffffffffu, x, o));
        smax[t] = x;
    }
    __syncthreads();
    const float M = smax[0];

    float e = expf(v - M);
    float s = e;
#pragma unroll
    for (int o = 16; o > 0; o >>= 1) s += __shfl_xor_sync(0xffffffffu, s, o);
    if ((t & 31) == 0) ssum[t >> 5] = s;
    __syncthreads();
    if (t < 32) {
        float x = ssum[t];
#pragma unroll
        for (int o = 16; o > 0; o >>= 1) x += __shfl_xor_sync(0xffffffffu, x, o);
        ssum[t] = x;
    }
    __syncthreads();
    out[b * Dq + t] = e / ssum[0];
}

// ---------------------------------------------------------------------------
extern "C" void kernel_launch(void* const* d_in, const int* in_sizes, int n_in,
                              void* d_out, int out_size) {
    const float* emb = (const float*)d_in[0];   // [B, D, N]
    // d_in[1] = heatm (unused)
    const float* W   = (const float*)d_in[2];   // [D, D]
    float* out = (float*)d_out;                 // [B, N, 1]

    convert_W_k<<<Dq * Dq / 256, 256>>>(W);
    convert_E_k<<<dim3(32, 32, Bq), dim3(32, 8)>>>(emb);
    init_rowmax_k<<<(Bq * Dq + 1023) / 1024, 1024>>>();

    dim3 grid(Dq / BN, Dq / BM, Bq);   // (8, 8, 16)
    mma_gemm_k<true><<<grid, 256>>>();
    mma_gemm_k<false><<<grid, 256>>>();
    softmax_k<<<Bq, 1024>>>(out);
}

// round 5
// speedup vs baseline: 5.0462x; 1.2642x over previous
#include <cuda_runtime.h>
#include <cuda_bf16.h>
#include <math_constants.h>
#include <cstdint>

#define Dq 1024
#define Bq 16
#define BM 128
#define BN 256
#define BKB 64                       // K bytes (= fp8 elems) per stage
#define NCHUNK (Dq / BKB)            // 16
#define ASTR 80                      // padded row stride (64B data + 16B pad)
#define A_STAGE (BM * ASTR)          // 10240 B
#define B_STAGE (BN * ASTR)          // 20480 B
#define STAGE_BYTES (A_STAGE + B_STAGE)
#define SMEM_TOTAL (3 * STAGE_BYTES) // 92160 B

// ---- scratch (__device__ globals: allocation-free rule) --------------------
__device__ uint8_t g_W8 [(size_t)Dq * Dq];            // (64*W)[d][k] e4m3
__device__ uint8_t g_ET8[(size_t)Bq * Dq * Dq];       // E^T[b][n][d] e4m3
__device__ uint8_t g_T8 [(size_t)Bq * Dq * Dq];       // 64*Tt[b][n][d] e4m3
__device__ float g_rowmax[Bq * Dq];

// ---- helpers ---------------------------------------------------------------
__device__ __forceinline__ uint32_t smem_u32(const void* p) {
    uint32_t a;
    asm("{ .reg .u64 t; cvta.to.shared.u64 t, %1; cvt.u32.u64 %0, t; }" : "=r"(a) : "l"(p));
    return a;
}
__device__ __forceinline__ void cp16(uint32_t s, const void* g) {
    asm volatile("cp.async.cg.shared.global [%0], [%1], 16;\n" :: "r"(s), "l"(g));
}
__device__ __forceinline__ void cp_commit() { asm volatile("cp.async.commit_group;\n"); }
template <int N> __device__ __forceinline__ void cp_wait() {
    asm volatile("cp.async.wait_group %0;\n" :: "n"(N));
}
__device__ __forceinline__ void ldsm4(uint32_t* r, uint32_t addr) {
    asm volatile("ldmatrix.sync.aligned.m8n8.x4.shared.b16 {%0,%1,%2,%3}, [%4];"
                 : "=r"(r[0]), "=r"(r[1]), "=r"(r[2]), "=r"(r[3]) : "r"(addr));
}
__device__ __forceinline__ void mma_e4m3(float* d, const uint32_t* a, uint32_t b0, uint32_t b1) {
    asm volatile("mma.sync.aligned.m16n8k32.row.col.f32.e4m3.e4m3.f32 "
                 "{%0,%1,%2,%3}, {%4,%5,%6,%7}, {%8,%9}, {%0,%1,%2,%3};"
                 : "+f"(d[0]), "+f"(d[1]), "+f"(d[2]), "+f"(d[3])
                 : "r"(a[0]), "r"(a[1]), "r"(a[2]), "r"(a[3]), "r"(b0), "r"(b1));
}
// packs: low byte = lo, high byte = hi
__device__ __forceinline__ uint16_t cvt2_e4m3(float hi, float lo) {
    uint16_t r;
    asm("cvt.rn.satfinite.e4m3x2.f32 %0, %1, %2;" : "=h"(r) : "f"(hi), "f"(lo));
    return r;
}
__device__ __forceinline__ void atomicMaxF(float* addr, float val) {
    int old = __float_as_int(*addr);
    while (__int_as_float(old) < val) {
        int assumed = old;
        old = atomicCAS((int*)addr, assumed, __float_as_int(val));
        if (old == assumed) break;
    }
}

// ---- setup kernels ---------------------------------------------------------
__global__ void init_rowmax_k() {
    int i = blockIdx.x * blockDim.x + threadIdx.x;
    if (i < Bq * Dq) g_rowmax[i] = -CUDART_INF_F;
}
// W fp32 -> e4m3, scaled by 64 (keeps values out of subnormal range)
__global__ void convert_W_k(const float* __restrict__ W) {
    int i = blockIdx.x * 256 + threadIdx.x;        // handles 2 elems
    float2 v = ((const float2*)W)[i];
    ((uint16_t*)g_W8)[i] = cvt2_e4m3(v.y * 64.f, v.x * 64.f);
}
// E [b][d][n] fp32 -> g_ET8 [b][n][d] e4m3 (transpose via smem tile)
__global__ __launch_bounds__(256) void convert_E_k(const float* __restrict__ E) {
    __shared__ float tile[32][33];
    const int b = blockIdx.z;
    const int x0 = blockIdx.x * 32, y0 = blockIdx.y * 32;  // x = n, y = d
    const float* __restrict__ Eb = E + (size_t)b * Dq * Dq;
    const int t = threadIdx.x;
#pragma unroll
    for (int i = 0; i < 4; i++) {
        int idx = t + i * 256;
        int y = idx >> 5, x = idx & 31;
        tile[y][x] = Eb[(size_t)(y0 + y) * Dq + x0 + x];
    }
    __syncthreads();
    // each thread writes 4 consecutive d as one u32
    const int n = x0 + (t >> 3);
    const int d0 = (t & 7) * 4;
    float v0 = tile[d0 + 0][t >> 3], v1 = tile[d0 + 1][t >> 3];
    float v2 = tile[d0 + 2][t >> 3], v3 = tile[d0 + 3][t >> 3];
    uint32_t packed = (uint32_t)cvt2_e4m3(v1, v0) | ((uint32_t)cvt2_e4m3(v3, v2) << 16);
    *(uint32_t*)(g_ET8 + (size_t)b * Dq * Dq + (size_t)n * Dq + y0 + d0) = packed;
}

// ---- fp8 tensor-core GEMM ---------------------------------------------------
// MODE 0: C = ET[b] @ (64W)^T  -> g_T8 (e4m3)          [rows=n, cols=d]
// MODE 1: C = ET[b] @ T8[b]^T  -> fused rowmax (64*S)  [rows=n1, cols=n2]
template <int MODE>
__global__ __launch_bounds__(256) void fp8_gemm_k() {
    extern __shared__ char smem[];
    const uint32_t sbase = smem_u32(smem);
    const int t = threadIdx.x, lane = t & 31, wid = t >> 5;
    const int wm = wid >> 2, wn = wid & 3;          // warp grid 2(M) x 4(N)
    const int b = blockIdx.z;
    const int rowBase = blockIdx.y * BM;
    const int colBase = blockIdx.x * BN;

    const uint8_t* __restrict__ A = g_ET8 + (size_t)b * Dq * Dq;
    const uint8_t* __restrict__ Bm =
        (MODE == 0) ? g_W8 : (g_T8 + (size_t)b * Dq * Dq);

    float acc[4][8][4];
#pragma unroll
    for (int mb = 0; mb < 4; mb++)
#pragma unroll
        for (int nb = 0; nb < 8; nb++)
#pragma unroll
            for (int r = 0; r < 4; r++) acc[mb][nb][r] = 0.f;

    auto load_stage = [&](int c) {
        const int buf = c % 3;
        uint32_t sA = sbase + buf * STAGE_BYTES;
        uint32_t sB = sA + A_STAGE;
        const int k0 = c * BKB;
#pragma unroll
        for (int i = 0; i < 2; i++) {               // A: 128 rows x 4 x 16B
            int idx = t + i * 256;
            int r = idx >> 2, c16 = (idx & 3) * 16;
            cp16(sA + (uint32_t)(r * ASTR + c16),
                 A + (size_t)(rowBase + r) * Dq + k0 + c16);
        }
#pragma unroll
        for (int i = 0; i < 4; i++) {               // B: 256 rows x 4 x 16B
            int idx = t + i * 256;
            int r = idx >> 2, c16 = (idx & 3) * 16;
            cp16(sB + (uint32_t)(r * ASTR + c16),
                 Bm + (size_t)(colBase + r) * Dq + k0 + c16);
        }
        cp_commit();
    };

    load_stage(0);
    load_stage(1);

    for (int c = 0; c < NCHUNK; c++) {
        if (c == NCHUNK - 1) cp_wait<0>(); else cp_wait<1>();
        __syncthreads();
        if (c + 2 < NCHUNK) load_stage(c + 2);

        const int buf = c % 3;
        const uint32_t sA = sbase + buf * STAGE_BYTES + (uint32_t)(wm * 64) * ASTR;
        const uint32_t sB = sbase + buf * STAGE_BYTES + A_STAGE + (uint32_t)(wn * 64) * ASTR;
#pragma unroll
        for (int s = 0; s < 2; s++) {               // two k32 steps per stage
            const int k0 = s * 32;
            uint32_t af[4][4];
#pragma unroll
            for (int mb = 0; mb < 4; mb++)
                ldsm4(af[mb], sA + (uint32_t)((mb * 16 + (lane & 15)) * ASTR
                                              + k0 + (lane >> 4) * 16));
#pragma unroll
            for (int p = 0; p < 4; p++) {
                uint32_t bf[4];
                ldsm4(bf, sB + (uint32_t)((p * 16 + ((lane >> 4) << 3) + (lane & 7)) * ASTR
                                          + k0 + ((lane >> 3) & 1) * 16));
#pragma unroll
                for (int mb = 0; mb < 4; mb++) {
                    mma_e4m3(acc[mb][2 * p + 0], af[mb], bf[0], bf[1]);
                    mma_e4m3(acc[mb][2 * p + 1], af[mb], bf[2], bf[3]);
                }
            }
        }
    }

    if (MODE == 0) {
        uint8_t* __restrict__ dst = g_T8 + (size_t)b * Dq * Dq;
#pragma unroll
        for (int mb = 0; mb < 4; mb++) {
            int r0 = rowBase + wm * 64 + mb * 16 + (lane >> 2);
#pragma unroll
            for (int nb = 0; nb < 8; nb++) {
                int col = colBase + wn * 64 + nb * 8 + (lane & 3) * 2;
                *(uint16_t*)(dst + (size_t)r0 * Dq + col) =
                    cvt2_e4m3(acc[mb][nb][1], acc[mb][nb][0]);
                *(uint16_t*)(dst + (size_t)(r0 + 8) * Dq + col) =
                    cvt2_e4m3(acc[mb][nb][3], acc[mb][nb][2]);
            }
        }
    } else {
#pragma unroll
        for (int mb = 0; mb < 4; mb++) {
            float m0 = -CUDART_INF_F, m1 = -CUDART_INF_F;
#pragma unroll
            for (int nb = 0; nb < 8; nb++) {
                m0 = fmaxf(m0, fmaxf(acc[mb][nb][0], acc[mb][nb][1]));
                m1 = fmaxf(m1, fmaxf(acc[mb][nb][2], acc[mb][nb][3]));
            }
            m0 = fmaxf(m0, __shfl_xor_sync(0xffffffffu, m0, 1));
            m0 = fmaxf(m0, __shfl_xor_sync(0xffffffffu, m0, 2));
            m1 = fmaxf(m1, __shfl_xor_sync(0xffffffffu, m1, 1));
            m1 = fmaxf(m1, __shfl_xor_sync(0xffffffffu, m1, 2));
            if ((lane & 3) == 0) {
                int r0 = rowBase + wm * 64 + mb * 16 + (lane >> 2);
                atomicMaxF(&g_rowmax[b * Dq + r0], m0);
                atomicMaxF(&g_rowmax[b * Dq + r0 + 8], m1);
            }
        }
    }
}

// ---- softmax over tanh(rowmax/64) ------------------------------------------
__global__ __launch_bounds__(1024) void softmax_k(float* __restrict__ out) {
    const int b = blockIdx.x;
    const int t = threadIdx.x;
    __shared__ float smax[32];
    __shared__ float ssum[32];

    float v = tanhf(g_rowmax[b * Dq + t] * 0.015625f);   // /64 (W was pre-scaled)
    float m = v;
#pragma unroll
    for (int o = 16; o > 0; o >>= 1) m = fmaxf(m, __shfl_xor_sync(0xffffffffu, m, o));
    if ((t & 31) == 0) smax[t >> 5] = m;
    __syncthreads();
    if (t < 32) {
        float x = smax[t];
#pragma unroll
        for (int o = 16; o > 0; o >>= 1) x = fmaxf(x, __shfl_xor_sync(0xffffffffu, x, o));
        smax[t] = x;
    }
    __syncthreads();
    const float M = smax[0];
    float e = expf(v - M);
    float s = e;
#pragma unroll
    for (int o = 16; o > 0; o >>= 1) s += __shfl_xor_sync(0xffffffffu, s, o);
    if ((t & 31) == 0) ssum[t >> 5] = s;
    __syncthreads();
    if (t < 32) {
        float x = ssum[t];
#pragma unroll
        for (int o = 16; o > 0; o >>= 1) x += __shfl_xor_sync(0xffffffffu, x, o);
        ssum[t] = x;
    }
    __syncthreads();
    out[b * Dq + t] = e / ssum[0];
}

// -----------------------------------------------------------------------------
extern "C" void kernel_launch(void* const* d_in, const int* in_sizes, int n_in,
                              void* d_out, int out_size) {
    const float* emb = (const float*)d_in[0];   // [B, D, N]
    const float* W   = (const float*)d_in[2];   // [D, D]
    float* out = (float*)d_out;                 // [B, N, 1]

    cudaFuncSetAttribute(fp8_gemm_k<0>, cudaFuncAttributeMaxDynamicSharedMemorySize, SMEM_TOTAL);
    cudaFuncSetAttribute(fp8_gemm_k<1>, cudaFuncAttributeMaxDynamicSharedMemorySize, SMEM_TOTAL);

    convert_W_k<<<Dq * Dq / 512, 256>>>(W);
    convert_E_k<<<dim3(32, 32, Bq), 256>>>(emb);
    init_rowmax_k<<<(Bq * Dq + 1023) / 1024, 1024>>>();

    dim3 grid(Dq / BN, Dq / BM, Bq);   // (4, 8, 16)
    fp8_gemm_k<0><<<grid, 256, SMEM_TOTAL>>>();
    fp8_gemm_k<1><<<grid, 256, SMEM_TOTAL>>>();
    softmax_k<<<Bq, 1024>>>(out);
}

// round 6
// speedup vs baseline: 5.3093x; 1.0521x over previous
#include <cuda_runtime.h>
#include <cuda_bf16.h>
#include <math_constants.h>
#include <cstdint>

#define Dq 1024
#define Bq 16
#define BM 128
#define BN 256
#define BKB 64                       // K bytes (= fp8 elems) per stage
#define NCHUNK (Dq / BKB)            // 16
#define ASTR 80                      // padded row stride (64B data + 16B pad)
#define A_STAGE (BM * ASTR)          // 10240 B
#define B_STAGE (BN * ASTR)          // 20480 B
#define STAGE_BYTES (A_STAGE + B_STAGE)
#define SMEM_TOTAL (3 * STAGE_BYTES) // 92160 B
#define NT 512

// ---- scratch (__device__ globals: allocation-free rule) --------------------
__device__ uint8_t g_W8 [(size_t)Dq * Dq];            // (64*W)[d][k] e4m3
__device__ uint8_t g_ET8[(size_t)Bq * Dq * Dq];       // E^T[b][n][d] e4m3
__device__ uint8_t g_T8 [(size_t)Bq * Dq * Dq];       // 64*Tt[b][n][d] e4m3
__device__ float g_rowmax[Bq * Dq];

// ---- helpers ---------------------------------------------------------------
__device__ __forceinline__ uint32_t smem_u32(const void* p) {
    uint32_t a;
    asm("{ .reg .u64 t; cvta.to.shared.u64 t, %1; cvt.u32.u64 %0, t; }" : "=r"(a) : "l"(p));
    return a;
}
__device__ __forceinline__ void cp16(uint32_t s, const void* g) {
    asm volatile("cp.async.cg.shared.global [%0], [%1], 16;\n" :: "r"(s), "l"(g));
}
__device__ __forceinline__ void cp_commit() { asm volatile("cp.async.commit_group;\n"); }
template <int N> __device__ __forceinline__ void cp_wait() {
    asm volatile("cp.async.wait_group %0;\n" :: "n"(N));
}
__device__ __forceinline__ void ldsm4(uint32_t* r, uint32_t addr) {
    asm volatile("ldmatrix.sync.aligned.m8n8.x4.shared.b16 {%0,%1,%2,%3}, [%4];"
                 : "=r"(r[0]), "=r"(r[1]), "=r"(r[2]), "=r"(r[3]) : "r"(addr));
}
__device__ __forceinline__ void mma_e4m3(float* d, const uint32_t* a, uint32_t b0, uint32_t b1) {
    asm volatile("mma.sync.aligned.m16n8k32.row.col.f32.e4m3.e4m3.f32 "
                 "{%0,%1,%2,%3}, {%4,%5,%6,%7}, {%8,%9}, {%0,%1,%2,%3};"
                 : "+f"(d[0]), "+f"(d[1]), "+f"(d[2]), "+f"(d[3])
                 : "r"(a[0]), "r"(a[1]), "r"(a[2]), "r"(a[3]), "r"(b0), "r"(b1));
}
// packs: low byte = lo, high byte = hi
__device__ __forceinline__ uint16_t cvt2_e4m3(float hi, float lo) {
    uint16_t r;
    asm("cvt.rn.satfinite.e4m3x2.f32 %0, %1, %2;" : "=h"(r) : "f"(hi), "f"(lo));
    return r;
}
__device__ __forceinline__ void atomicMaxF(float* addr, float val) {
    int old = __float_as_int(*addr);
    while (__int_as_float(old) < val) {
        int assumed = old;
        old = atomicCAS((int*)addr, assumed, __float_as_int(val));
        if (old == assumed) break;
    }
}

// ---- setup kernels ---------------------------------------------------------
__global__ void init_rowmax_k() {
    int i = blockIdx.x * blockDim.x + threadIdx.x;
    if (i < Bq * Dq) g_rowmax[i] = -CUDART_INF_F;
}
// W fp32 -> e4m3, scaled by 64 (keeps values out of subnormal range)
__global__ void convert_W_k(const float* __restrict__ W) {
    int i = blockIdx.x * 256 + threadIdx.x;        // handles 2 elems
    float2 v = ((const float2*)W)[i];
    ((uint16_t*)g_W8)[i] = cvt2_e4m3(v.y * 64.f, v.x * 64.f);
}
// E [b][d][n] fp32 -> g_ET8 [b][n][d] e4m3 (transpose via smem tile)
__global__ __launch_bounds__(256) void convert_E_k(const float* __restrict__ E) {
    __shared__ float tile[32][33];
    const int b = blockIdx.z;
    const int x0 = blockIdx.x * 32, y0 = blockIdx.y * 32;  // x = n, y = d
    const float* __restrict__ Eb = E + (size_t)b * Dq * Dq;
    const int t = threadIdx.x;
#pragma unroll
    for (int i = 0; i < 4; i++) {
        int idx = t + i * 256;
        int y = idx >> 5, x = idx & 31;
        tile[y][x] = Eb[(size_t)(y0 + y) * Dq + x0 + x];
    }
    __syncthreads();
    const int n = x0 + (t >> 3);
    const int d0 = (t & 7) * 4;
    float v0 = tile[d0 + 0][t >> 3], v1 = tile[d0 + 1][t >> 3];
    float v2 = tile[d0 + 2][t >> 3], v3 = tile[d0 + 3][t >> 3];
    uint32_t packed = (uint32_t)cvt2_e4m3(v1, v0) | ((uint32_t)cvt2_e4m3(v3, v2) << 16);
    *(uint32_t*)(g_ET8 + (size_t)b * Dq * Dq + (size_t)n * Dq + y0 + d0) = packed;
}

// ---- fp8 tensor-core GEMM ---------------------------------------------------
// 512 threads, warp grid 4(M) x 4(N), warp tile 32 x 64.
// MODE 0: C = ET[b] @ (64W)^T  -> g_T8 (e4m3)          [rows=n, cols=d]
// MODE 1: C = ET[b] @ T8[b]^T  -> fused rowmax (64*S)  [rows=n1, cols=n2]
template <int MODE>
__global__ __launch_bounds__(NT) void fp8_gemm_k() {
    extern __shared__ char smem[];
    const uint32_t sbase = smem_u32(smem);
    const int t = threadIdx.x, lane = t & 31, wid = t >> 5;
    const int wm = wid >> 2, wn = wid & 3;          // 4(M) x 4(N)
    const int b = blockIdx.z;
    const int rowBase = blockIdx.y * BM;
    const int colBase = blockIdx.x * BN;

    const uint8_t* __restrict__ A = g_ET8 + (size_t)b * Dq * Dq;
    const uint8_t* __restrict__ Bm =
        (MODE == 0) ? g_W8 : (g_T8 + (size_t)b * Dq * Dq);

    float acc[2][8][4];
#pragma unroll
    for (int mb = 0; mb < 2; mb++)
#pragma unroll
        for (int nb = 0; nb < 8; nb++)
#pragma unroll
            for (int r = 0; r < 4; r++) acc[mb][nb][r] = 0.f;

    auto load_stage = [&](int c) {
        const int buf = c % 3;
        uint32_t sA = sbase + buf * STAGE_BYTES;
        uint32_t sB = sA + A_STAGE;
        const int k0 = c * BKB;
        {   // A: 128 rows x 4 x 16B = 512 cp16 (1 per thread)
            int r = t >> 2, c16 = (t & 3) * 16;
            cp16(sA + (uint32_t)(r * ASTR + c16),
                 A + (size_t)(rowBase + r) * Dq + k0 + c16);
        }
#pragma unroll
        for (int i = 0; i < 2; i++) {               // B: 256 rows x 4 x 16B
            int idx = t + i * NT;
            int r = idx >> 2, c16 = (idx & 3) * 16;
            cp16(sB + (uint32_t)(r * ASTR + c16),
                 Bm + (size_t)(colBase + r) * Dq + k0 + c16);
        }
        cp_commit();
    };

    load_stage(0);
    load_stage(1);

    for (int c = 0; c < NCHUNK; c++) {
        if (c == NCHUNK - 1) cp_wait<0>(); else cp_wait<1>();
        __syncthreads();
        if (c + 2 < NCHUNK) load_stage(c + 2);

        const int buf = c % 3;
        const uint32_t sA = sbase + buf * STAGE_BYTES + (uint32_t)(wm * 32) * ASTR;
        const uint32_t sB = sbase + buf * STAGE_BYTES + A_STAGE + (uint32_t)(wn * 64) * ASTR;
#pragma unroll
        for (int s = 0; s < 2; s++) {               // two k32 steps per stage
            const int k0 = s * 32;
            uint32_t af[2][4];
#pragma unroll
            for (int mb = 0; mb < 2; mb++)
                ldsm4(af[mb], sA + (uint32_t)((mb * 16 + (lane & 15)) * ASTR
                                              + k0 + (lane >> 4) * 16));
#pragma unroll
            for (int p = 0; p < 4; p++) {
                uint32_t bf[4];
                ldsm4(bf, sB + (uint32_t)((p * 16 + ((lane >> 4) << 3) + (lane & 7)) * ASTR
                                          + k0 + ((lane >> 3) & 1) * 16));
#pragma unroll
                for (int mb = 0; mb < 2; mb++) {
                    mma_e4m3(acc[mb][2 * p + 0], af[mb], bf[0], bf[1]);
                    mma_e4m3(acc[mb][2 * p + 1], af[mb], bf[2], bf[3]);
                }
            }
        }
    }

    if (MODE == 0) {
        uint8_t* __restrict__ dst = g_T8 + (size_t)b * Dq * Dq;
#pragma unroll
        for (int mb = 0; mb < 2; mb++) {
            int r0 = rowBase + wm * 32 + mb * 16 + (lane >> 2);
#pragma unroll
            for (int nb = 0; nb < 8; nb++) {
                int col = colBase + wn * 64 + nb * 8 + (lane & 3) * 2;
                *(uint16_t*)(dst + (size_t)r0 * Dq + col) =
                    cvt2_e4m3(acc[mb][nb][1], acc[mb][nb][0]);
                *(uint16_t*)(dst + (size_t)(r0 + 8) * Dq + col) =
                    cvt2_e4m3(acc[mb][nb][3], acc[mb][nb][2]);
            }
        }
    } else {
#pragma unroll
        for (int mb = 0; mb < 2; mb++) {
            float m0 = -CUDART_INF_F, m1 = -CUDART_INF_F;
#pragma unroll
            for (int nb = 0; nb < 8; nb++) {
                m0 = fmaxf(m0, fmaxf(acc[mb][nb][0], acc[mb][nb][1]));
                m1 = fmaxf(m1, fmaxf(acc[mb][nb][2], acc[mb][nb][3]));
            }
            m0 = fmaxf(m0, __shfl_xor_sync(0xffffffffu, m0, 1));
            m0 = fmaxf(m0, __shfl_xor_sync(0xffffffffu, m0, 2));
            m1 = fmaxf(m1, __shfl_xor_sync(0xffffffffu, m1, 1));
            m1 = fmaxf(m1, __shfl_xor_sync(0xffffffffu, m1, 2));
            if ((lane & 3) == 0) {
                int r0 = rowBase + wm * 32 + mb * 16 + (lane >> 2);
                atomicMaxF(&g_rowmax[b * Dq + r0], m0);
                atomicMaxF(&g_rowmax[b * Dq + r0 + 8], m1);
            }
        }
    }
}

// ---- softmax over tanh(rowmax/64) ------------------------------------------
__global__ __launch_bounds__(1024) void softmax_k(float* __restrict__ out) {
    const int b = blockIdx.x;
    const int t = threadIdx.x;
    __shared__ float smax[32];
    __shared__ float ssum[32];

    float v = tanhf(g_rowmax[b * Dq + t] * 0.015625f);   // /64 (W was pre-scaled)
    float m = v;
#pragma unroll
    for (int o = 16; o > 0; o >>= 1) m = fmaxf(m, __shfl_xor_sync(0xffffffffu, m, o));
    if ((t & 31) == 0) smax[t >> 5] = m;
    __syncthreads();
    if (t < 32) {
        float x = smax[t];
#pragma unroll
        for (int o = 16; o > 0; o >>= 1) x = fmaxf(x, __shfl_xor_sync(0xffffffffu, x, o));
        smax[t] = x;
    }
    __syncthreads();
    const float M = smax[0];
    float e = expf(v - M);
    float s = e;
#pragma unroll
    for (int o = 16; o > 0; o >>= 1) s += __shfl_xor_sync(0xffffffffu, s, o);
    if ((t & 31) == 0) ssum[t >> 5] = s;
    __syncthreads();
    if (t < 32) {
        float x = ssum[t];
#pragma unroll
        for (int o = 16; o > 0; o >>= 1) x += __shfl_xor_sync(0xffffffffu, x, o);
        ssum[t] = x;
    }
    __syncthreads();
    out[b * Dq + t] = e / ssum[0];
}

// -----------------------------------------------------------------------------
extern "C" void kernel_launch(void* const* d_in, const int* in_sizes, int n_in,
                              void* d_out, int out_size) {
    const float* emb = (const float*)d_in[0];   // [B, D, N]
    const float* W   = (const float*)d_in[2];   // [D, D]
    float* out = (float*)d_out;                 // [B, N, 1]

    cudaFuncSetAttribute(fp8_gemm_k<0>, cudaFuncAttributeMaxDynamicSharedMemorySize, SMEM_TOTAL);
    cudaFuncSetAttribute(fp8_gemm_k<1>, cudaFuncAttributeMaxDynamicSharedMemorySize, SMEM_TOTAL);

    convert_W_k<<<Dq * Dq / 512, 256>>>(W);
    convert_E_k<<<dim3(32, 32, Bq), 256>>>(emb);
    init_rowmax_k<<<(Bq * Dq + 1023) / 1024, 1024>>>();

    dim3 grid(Dq / BN, Dq / BM, Bq);   // (4, 8, 16)
    fp8_gemm_k<0><<<grid, NT, SMEM_TOTAL>>>();
    fp8_gemm_k<1><<<grid, NT, SMEM_TOTAL>>>();
    softmax_k<<<Bq, 1024>>>(out);
}

// round 7
// speedup vs baseline: 6.4771x; 1.2200x over previous
#include <cuda_runtime.h>
#include <cuda_bf16.h>
#include <math_constants.h>
#include <cstdint>

#define Dq 1024
#define Bq 16
#define BM 128
#define BN 128
#define BKB 64                        // K bytes per stage
#define NCHUNK (Dq / BKB)             // 16
#define ASTR 80                       // padded row stride
#define A_STAGE (BM * ASTR)           // 10240 B
#define B_STAGE (BN * ASTR)           // 10240 B
#define STAGE_BYTES (A_STAGE + B_STAGE)   // 20480 B
#define NSTAGE 4
#define SMEM_TOTAL (NSTAGE * STAGE_BYTES) // 81920 B
#define NT 256

// ---- scratch (__device__ globals) ------------------------------------------
__device__ uint8_t g_W8 [(size_t)Dq * Dq];            // (64*W)[d][k] e4m3
__device__ uint8_t g_ET8[(size_t)Bq * Dq * Dq];       // E^T[b][n][d] e4m3
__device__ uint8_t g_T8 [(size_t)Bq * Dq * Dq];       // 64*Tt[b][n][d] e4m3
__device__ float g_rowmax[Bq * Dq];

// ---- helpers ---------------------------------------------------------------
__device__ __forceinline__ uint32_t smem_u32(const void* p) {
    uint32_t a;
    asm("{ .reg .u64 t; cvta.to.shared.u64 t, %1; cvt.u32.u64 %0, t; }" : "=r"(a) : "l"(p));
    return a;
}
__device__ __forceinline__ void cp16(uint32_t s, const void* g) {
    asm volatile("cp.async.cg.shared.global [%0], [%1], 16;\n" :: "r"(s), "l"(g));
}
__device__ __forceinline__ void cp_commit() { asm volatile("cp.async.commit_group;\n"); }
template <int N> __device__ __forceinline__ void cp_wait() {
    asm volatile("cp.async.wait_group %0;\n" :: "n"(N));
}
__device__ __forceinline__ void ldsm4(uint32_t* r, uint32_t addr) {
    asm volatile("ldmatrix.sync.aligned.m8n8.x4.shared.b16 {%0,%1,%2,%3}, [%4];"
                 : "=r"(r[0]), "=r"(r[1]), "=r"(r[2]), "=r"(r[3]) : "r"(addr));
}
__device__ __forceinline__ void mma_e4m3(float* d, const uint32_t* a, uint32_t b0, uint32_t b1) {
    asm volatile("mma.sync.aligned.m16n8k32.row.col.f32.e4m3.e4m3.f32 "
                 "{%0,%1,%2,%3}, {%4,%5,%6,%7}, {%8,%9}, {%0,%1,%2,%3};"
                 : "+f"(d[0]), "+f"(d[1]), "+f"(d[2]), "+f"(d[3])
                 : "r"(a[0]), "r"(a[1]), "r"(a[2]), "r"(a[3]), "r"(b0), "r"(b1));
}
__device__ __forceinline__ uint16_t cvt2_e4m3(float hi, float lo) {
    uint16_t r;
    asm("cvt.rn.satfinite.e4m3x2.f32 %0, %1, %2;" : "=h"(r) : "f"(hi), "f"(lo));
    return r;
}
__device__ __forceinline__ void atomicMaxF(float* addr, float val) {
    int old = __float_as_int(*addr);
    while (__int_as_float(old) < val) {
        int assumed = old;
        old = atomicCAS((int*)addr, assumed, __float_as_int(val));
        if (old == assumed) break;
    }
}

// ---- setup kernels ---------------------------------------------------------
__global__ void init_rowmax_k() {
    int i = blockIdx.x * blockDim.x + threadIdx.x;
    if (i < Bq * Dq) g_rowmax[i] = -CUDART_INF_F;
}
__global__ void convert_W_k(const float* __restrict__ W) {
    int i = blockIdx.x * 256 + threadIdx.x;
    float2 v = ((const float2*)W)[i];
    ((uint16_t*)g_W8)[i] = cvt2_e4m3(v.y * 64.f, v.x * 64.f);
}
__global__ __launch_bounds__(256) void convert_E_k(const float* __restrict__ E) {
    __shared__ float tile[32][33];
    const int b = blockIdx.z;
    const int x0 = blockIdx.x * 32, y0 = blockIdx.y * 32;
    const float* __restrict__ Eb = E + (size_t)b * Dq * Dq;
    const int t = threadIdx.x;
#pragma unroll
    for (int i = 0; i < 4; i++) {
        int idx = t + i * 256;
        int y = idx >> 5, x = idx & 31;
        tile[y][x] = Eb[(size_t)(y0 + y) * Dq + x0 + x];
    }
    __syncthreads();
    const int n = x0 + (t >> 3);
    const int d0 = (t & 7) * 4;
    float v0 = tile[d0 + 0][t >> 3], v1 = tile[d0 + 1][t >> 3];
    float v2 = tile[d0 + 2][t >> 3], v3 = tile[d0 + 3][t >> 3];
    uint32_t packed = (uint32_t)cvt2_e4m3(v1, v0) | ((uint32_t)cvt2_e4m3(v3, v2) << 16);
    *(uint32_t*)(g_ET8 + (size_t)b * Dq * Dq + (size_t)n * Dq + y0 + d0) = packed;
}

// ---- fp8 tensor-core GEMM ---------------------------------------------------
// 256 threads, warp grid 2(M) x 4(N), warp tile 64 x 32, 4-stage pipeline.
// MODE 0: C = ET[b] @ (64W)^T  -> g_T8 (e4m3)
// MODE 1: C = ET[b] @ T8[b]^T  -> fused rowmax
template <int MODE>
__global__ __launch_bounds__(NT, 2) void fp8_gemm_k() {
    extern __shared__ char smem[];
    const uint32_t sbase = smem_u32(smem);
    const int t = threadIdx.x, lane = t & 31, wid = t >> 5;
    const int wm = wid >> 2, wn = wid & 3;          // 2(M) x 4(N)
    const int b = blockIdx.z;
    const int rowBase = blockIdx.y * BM;
    const int colBase = blockIdx.x * BN;

    const uint8_t* __restrict__ A = g_ET8 + (size_t)b * Dq * Dq;
    const uint8_t* __restrict__ Bm =
        (MODE == 0) ? g_W8 : (g_T8 + (size_t)b * Dq * Dq);

    float acc[4][4][4];   // [mb 16-row][nb 8-col][frag]
#pragma unroll
    for (int mb = 0; mb < 4; mb++)
#pragma unroll
        for (int nb = 0; nb < 4; nb++)
#pragma unroll
            for (int r = 0; r < 4; r++) acc[mb][nb][r] = 0.f;

    auto load_stage = [&](int c) {
        const int buf = c & (NSTAGE - 1);
        uint32_t sA = sbase + buf * STAGE_BYTES;
        uint32_t sB = sA + A_STAGE;
        const int k0 = c * BKB;
#pragma unroll
        for (int i = 0; i < 2; i++) {               // A: 128 rows x 4 x 16B
            int idx = t + i * NT;
            int r = idx >> 2, c16 = (idx & 3) * 16;
            cp16(sA + (uint32_t)(r * ASTR + c16),
                 A + (size_t)(rowBase + r) * Dq + k0 + c16);
        }
#pragma unroll
        for (int i = 0; i < 2; i++) {               // B: 128 rows x 4 x 16B
            int idx = t + i * NT;
            int r = idx >> 2, c16 = (idx & 3) * 16;
            cp16(sB + (uint32_t)(r * ASTR + c16),
                 Bm + (size_t)(colBase + r) * Dq + k0 + c16);
        }
        cp_commit();
    };

    load_stage(0);
    load_stage(1);
    load_stage(2);

    for (int c = 0; c < NCHUNK; c++) {
        if (c + 2 < NCHUNK)      cp_wait<2>();
        else if (c + 1 < NCHUNK) cp_wait<1>();
        else                     cp_wait<0>();
        __syncthreads();
        if (c + 3 < NCHUNK) load_stage(c + 3);

        const int buf = c & (NSTAGE - 1);
        const uint32_t sA = sbase + buf * STAGE_BYTES + (uint32_t)(wm * 64) * ASTR;
        const uint32_t sB = sbase + buf * STAGE_BYTES + A_STAGE + (uint32_t)(wn * 32) * ASTR;
#pragma unroll
        for (int s = 0; s < 2; s++) {               // two k32 steps per stage
            const int k0 = s * 32;
            uint32_t af[4][4];
#pragma unroll
            for (int mb = 0; mb < 4; mb++)
                ldsm4(af[mb], sA + (uint32_t)((mb * 16 + (lane & 15)) * ASTR
                                              + k0 + (lane >> 4) * 16));
#pragma unroll
            for (int p = 0; p < 2; p++) {           // two n16 groups
                uint32_t bf[4];
                ldsm4(bf, sB + (uint32_t)((p * 16 + ((lane >> 4) << 3) + (lane & 7)) * ASTR
                                          + k0 + ((lane >> 3) & 1) * 16));
#pragma unroll
                for (int mb = 0; mb < 4; mb++) {
                    mma_e4m3(acc[mb][2 * p + 0], af[mb], bf[0], bf[1]);
                    mma_e4m3(acc[mb][2 * p + 1], af[mb], bf[2], bf[3]);
                }
            }
        }
    }

    if (MODE == 0) {
        uint8_t* __restrict__ dst = g_T8 + (size_t)b * Dq * Dq;
#pragma unroll
        for (int mb = 0; mb < 4; mb++) {
            int r0 = rowBase + wm * 64 + mb * 16 + (lane >> 2);
#pragma unroll
            for (int nb = 0; nb < 4; nb++) {
                int col = colBase + wn * 32 + nb * 8 + (lane & 3) * 2;
                *(uint16_t*)(dst + (size_t)r0 * Dq + col) =
                    cvt2_e4m3(acc[mb][nb][1], acc[mb][nb][0]);
                *(uint16_t*)(dst + (size_t)(r0 + 8) * Dq + col) =
                    cvt2_e4m3(acc[mb][nb][3], acc[mb][nb][2]);
            }
        }
    } else {
#pragma unroll
        for (int mb = 0; mb < 4; mb++) {
            float m0 = -CUDART_INF_F, m1 = -CUDART_INF_F;
#pragma unroll
            for (int nb = 0; nb < 4; nb++) {
                m0 = fmaxf(m0, fmaxf(acc[mb][nb][0], acc[mb][nb][1]));
                m1 = fmaxf(m1, fmaxf(acc[mb][nb][2], acc[mb][nb][3]));
            }
            m0 = fmaxf(m0, __shfl_xor_sync(0xffffffffu, m0, 1));
            m0 = fmaxf(m0, __shfl_xor_sync(0xffffffffu, m0, 2));
            m1 = fmaxf(m1, __shfl_xor_sync(0xffffffffu, m1, 1));
            m1 = fmaxf(m1, __shfl_xor_sync(0xffffffffu, m1, 2));
            if ((lane & 3) == 0) {
                int r0 = rowBase + wm * 64 + mb * 16 + (lane >> 2);
                atomicMaxF(&g_rowmax[b * Dq + r0], m0);
                atomicMaxF(&g_rowmax[b * Dq + r0 + 8], m1);
            }
        }
    }
}

// ---- softmax over tanh(rowmax/64) ------------------------------------------
__global__ __launch_bounds__(1024) void softmax_k(float* __restrict__ out) {
    const int b = blockIdx.x;
    const int t = threadIdx.x;
    __shared__ float smax[32];
    __shared__ float ssum[32];

    float v = tanhf(g_rowmax[b * Dq + t] * 0.015625f);
    float m = v;
#pragma unroll
    for (int o = 16; o > 0; o >>= 1) m = fmaxf(m, __shfl_xor_sync(0xffffffffu, m, o));
    if ((t & 31) == 0) smax[t >> 5] = m;
    __syncthreads();
    if (t < 32) {
        float x = smax[t];
#pragma unroll
        for (int o = 16; o > 0; o >>= 1) x = fmaxf(x, __shfl_xor_sync(0xffffffffu, x, o));
        smax[t] = x;
    }
    __syncthreads();
    const float M = smax[0];
    float e = expf(v - M);
    float s = e;
#pragma unroll
    for (int o = 16; o > 0; o >>= 1) s += __shfl_xor_sync(0xffffffffu, s, o);
    if ((t & 31) == 0) ssum[t >> 5] = s;
    __syncthreads();
    if (t < 32) {
        float x = ssum[t];
#pragma unroll
        for (int o = 16; o > 0; o >>= 1) x += __shfl_xor_sync(0xffffffffu, x, o);
        ssum[t] = x;
    }
    __syncthreads();
    out[b * Dq + t] = e / ssum[0];
}

// -----------------------------------------------------------------------------
extern "C" void kernel_launch(void* const* d_in, const int* in_sizes, int n_in,
                              void* d_out, int out_size) {
    const float* emb = (const float*)d_in[0];   // [B, D, N]
    const float* W   = (const float*)d_in[2];   // [D, D]
    float* out = (float*)d_out;                 // [B, N, 1]

    cudaFuncSetAttribute(fp8_gemm_k<0>, cudaFuncAttributeMaxDynamicSharedMemorySize, SMEM_TOTAL);
    cudaFuncSetAttribute(fp8_gemm_k<1>, cudaFuncAttributeMaxDynamicSharedMemorySize, SMEM_TOTAL);

    convert_W_k<<<Dq * Dq / 512, 256>>>(W);
    convert_E_k<<<dim3(32, 32, Bq), 256>>>(emb);
    init_rowmax_k<<<(Bq * Dq + 1023) / 1024, 1024>>>();

    dim3 grid(Dq / BN, Dq / BM, Bq);   // (8, 8, 16)
    fp8_gemm_k<0><<<grid, NT, SMEM_TOTAL>>>();
    fp8_gemm_k<1><<<grid, NT, SMEM_TOTAL>>>();
    softmax_k<<<Bq, 1024>>>(out);
}

// round 8
// speedup vs baseline: 6.5520x; 1.0116x over previous
#include <cuda_runtime.h>
#include <cuda_bf16.h>
#include <math_constants.h>
#include <cstdint>

#define Dq 1024
#define Bq 16
#define BM 128
#define BN 128
#define BKB 128                       // K bytes per stage (full row)
#define NCHUNK (Dq / BKB)             // 8
#define ASTR 144                      // padded row stride (128B + 16B)
#define A_STAGE (BM * ASTR)           // 18432 B
#define B_STAGE (BN * ASTR)           // 18432 B
#define STAGE_BYTES (A_STAGE + B_STAGE)   // 36864 B
#define NSTAGE 3
#define SMEM_TOTAL (NSTAGE * STAGE_BYTES) // 110592 B
#define NT 256

// ---- scratch (__device__ globals) ------------------------------------------
__device__ uint8_t g_W8 [(size_t)Dq * Dq];            // (64*W)[d][k] e4m3
__device__ uint8_t g_ET8[(size_t)Bq * Dq * Dq];       // E^T[b][n][d] e4m3
__device__ uint8_t g_T8 [(size_t)Bq * Dq * Dq];       // 64*Tt[b][n][d] e4m3
__device__ float g_rowmax[Bq * Dq];

// ---- helpers ---------------------------------------------------------------
__device__ __forceinline__ uint32_t smem_u32(const void* p) {
    uint32_t a;
    asm("{ .reg .u64 t; cvta.to.shared.u64 t, %1; cvt.u32.u64 %0, t; }" : "=r"(a) : "l"(p));
    return a;
}
__device__ __forceinline__ void cp16(uint32_t s, const void* g) {
    asm volatile("cp.async.cg.shared.global [%0], [%1], 16;\n" :: "r"(s), "l"(g));
}
__device__ __forceinline__ void cp_commit() { asm volatile("cp.async.commit_group;\n"); }
template <int N> __device__ __forceinline__ void cp_wait() {
    asm volatile("cp.async.wait_group %0;\n" :: "n"(N));
}
__device__ __forceinline__ void ldsm4(uint32_t* r, uint32_t addr) {
    asm volatile("ldmatrix.sync.aligned.m8n8.x4.shared.b16 {%0,%1,%2,%3}, [%4];"
                 : "=r"(r[0]), "=r"(r[1]), "=r"(r[2]), "=r"(r[3]) : "r"(addr));
}
__device__ __forceinline__ void mma_e4m3(float* d, const uint32_t* a, uint32_t b0, uint32_t b1) {
    asm volatile("mma.sync.aligned.m16n8k32.row.col.f32.e4m3.e4m3.f32 "
                 "{%0,%1,%2,%3}, {%4,%5,%6,%7}, {%8,%9}, {%0,%1,%2,%3};"
                 : "+f"(d[0]), "+f"(d[1]), "+f"(d[2]), "+f"(d[3])
                 : "r"(a[0]), "r"(a[1]), "r"(a[2]), "r"(a[3]), "r"(b0), "r"(b1));
}
__device__ __forceinline__ uint16_t cvt2_e4m3(float hi, float lo) {
    uint16_t r;
    asm("cvt.rn.satfinite.e4m3x2.f32 %0, %1, %2;" : "=h"(r) : "f"(hi), "f"(lo));
    return r;
}
__device__ __forceinline__ void atomicMaxF(float* addr, float val) {
    int old = __float_as_int(*addr);
    while (__int_as_float(old) < val) {
        int assumed = old;
        old = atomicCAS((int*)addr, assumed, __float_as_int(val));
        if (old == assumed) break;
    }
}

// ---- setup kernels ---------------------------------------------------------
__global__ void init_rowmax_k() {
    int i = blockIdx.x * blockDim.x + threadIdx.x;
    if (i < Bq * Dq) g_rowmax[i] = -CUDART_INF_F;
}
__global__ void convert_W_k(const float* __restrict__ W) {
    int i = blockIdx.x * 256 + threadIdx.x;
    float2 v = ((const float2*)W)[i];
    ((uint16_t*)g_W8)[i] = cvt2_e4m3(v.y * 64.f, v.x * 64.f);
}
__global__ __launch_bounds__(256) void convert_E_k(const float* __restrict__ E) {
    __shared__ float tile[32][33];
    const int b = blockIdx.z;
    const int x0 = blockIdx.x * 32, y0 = blockIdx.y * 32;
    const float* __restrict__ Eb = E + (size_t)b * Dq * Dq;
    const int t = threadIdx.x;
#pragma unroll
    for (int i = 0; i < 4; i++) {
        int idx = t + i * 256;
        int y = idx >> 5, x = idx & 31;
        tile[y][x] = Eb[(size_t)(y0 + y) * Dq + x0 + x];
    }
    __syncthreads();
    const int n = x0 + (t >> 3);
    const int d0 = (t & 7) * 4;
    float v0 = tile[d0 + 0][t >> 3], v1 = tile[d0 + 1][t >> 3];
    float v2 = tile[d0 + 2][t >> 3], v3 = tile[d0 + 3][t >> 3];
    uint32_t packed = (uint32_t)cvt2_e4m3(v1, v0) | ((uint32_t)cvt2_e4m3(v3, v2) << 16);
    *(uint32_t*)(g_ET8 + (size_t)b * Dq * Dq + (size_t)n * Dq + y0 + d0) = packed;
}

// ---- fp8 tensor-core GEMM ---------------------------------------------------
// 256 threads, warp grid 2(M) x 4(N), warp tile 64 x 32, 3-stage / K128 chunks.
// MODE 0: C = ET[b] @ (64W)^T  -> g_T8 (e4m3)
// MODE 1: C = ET[b] @ T8[b]^T  -> fused rowmax
template <int MODE>
__global__ __launch_bounds__(NT, 2) void fp8_gemm_k() {
    extern __shared__ char smem[];
    const uint32_t sbase = smem_u32(smem);
    const int t = threadIdx.x, lane = t & 31, wid = t >> 5;
    const int wm = wid >> 2, wn = wid & 3;          // 2(M) x 4(N)
    const int b = blockIdx.z;
    const int rowBase = blockIdx.y * BM;
    const int colBase = blockIdx.x * BN;

    const uint8_t* __restrict__ A = g_ET8 + (size_t)b * Dq * Dq;
    const uint8_t* __restrict__ Bm =
        (MODE == 0) ? g_W8 : (g_T8 + (size_t)b * Dq * Dq);

    float acc[4][4][4];
#pragma unroll
    for (int mb = 0; mb < 4; mb++)
#pragma unroll
        for (int nb = 0; nb < 4; nb++)
#pragma unroll
            for (int r = 0; r < 4; r++) acc[mb][nb][r] = 0.f;

    // hoisted fragment smem offsets (within a stage)
    uint32_t aoff[4], boff[2];
#pragma unroll
    for (int mb = 0; mb < 4; mb++)
        aoff[mb] = (uint32_t)((wm * 64 + mb * 16 + (lane & 15)) * ASTR + (lane >> 4) * 16);
#pragma unroll
    for (int p = 0; p < 2; p++)
        boff[p] = (uint32_t)((wn * 32 + p * 16 + ((lane >> 4) << 3) + (lane & 7)) * ASTR
                             + ((lane >> 3) & 1) * 16) + A_STAGE;

    // hoisted load coords: each thread does 4 A rows + 4 B rows (16B each)
    const int ldRow = t >> 2, ldCol = (t & 3) * 32 + ((t >> 2) & 1) * 16; // 2 cols/row pattern
    // simpler: 8 cp16/thread: rows t>>1? use straightforward mapping below.

    auto load_stage = [&](int c) {
        const int buf = c % NSTAGE;
        uint32_t sA = sbase + buf * STAGE_BYTES;
        uint32_t sB = sA + A_STAGE;
        const int k0 = c * BKB;
#pragma unroll
        for (int i = 0; i < 4; i++) {               // A: 128 rows x 8 x 16B
            int idx = t + i * NT;
            int r = idx >> 3, c16 = (idx & 7) * 16;
            cp16(sA + (uint32_t)(r * ASTR + c16),
                 A + (size_t)(rowBase + r) * Dq + k0 + c16);
        }
#pragma unroll
        for (int i = 0; i < 4; i++) {               // B: 128 rows x 8 x 16B
            int idx = t + i * NT;
            int r = idx >> 3, c16 = (idx & 7) * 16;
            cp16(sB + (uint32_t)(r * ASTR + c16),
                 Bm + (size_t)(colBase + r) * Dq + k0 + c16);
        }
        cp_commit();
    };

    load_stage(0);
    load_stage(1);
    load_stage(2);

    for (int c = 0; c < NCHUNK; c++) {
        if (c + 2 < NCHUNK)      cp_wait<2>();
        else if (c + 1 < NCHUNK) cp_wait<1>();
        else                     cp_wait<0>();
        __syncthreads();
        if (c + 3 < NCHUNK) load_stage(c + 3);

        const uint32_t stageBase = sbase + (uint32_t)((c % NSTAGE) * STAGE_BYTES);
#pragma unroll
        for (int s = 0; s < 4; s++) {               // four k32 steps per chunk
            const uint32_t k0 = s * 32;
            uint32_t af[4][4];
#pragma unroll
            for (int mb = 0; mb < 4; mb++)
                ldsm4(af[mb], stageBase + aoff[mb] + k0);
#pragma unroll
            for (int p = 0; p < 2; p++) {
                uint32_t bf[4];
                ldsm4(bf, stageBase + boff[p] + k0);
#pragma unroll
                for (int mb = 0; mb < 4; mb++) {
                    mma_e4m3(acc[mb][2 * p + 0], af[mb], bf[0], bf[1]);
                    mma_e4m3(acc[mb][2 * p + 1], af[mb], bf[2], bf[3]);
                }
            }
        }
        __syncthreads();
    }

    if (MODE == 0) {
        uint8_t* __restrict__ dst = g_T8 + (size_t)b * Dq * Dq;
#pragma unroll
        for (int mb = 0; mb < 4; mb++) {
            int r0 = rowBase + wm * 64 + mb * 16 + (lane >> 2);
#pragma unroll
            for (int nb = 0; nb < 4; nb++) {
                int col = colBase + wn * 32 + nb * 8 + (lane & 3) * 2;
                *(uint16_t*)(dst + (size_t)r0 * Dq + col) =
                    cvt2_e4m3(acc[mb][nb][1], acc[mb][nb][0]);
                *(uint16_t*)(dst + (size_t)(r0 + 8) * Dq + col) =
                    cvt2_e4m3(acc[mb][nb][3], acc[mb][nb][2]);
            }
        }
    } else {
#pragma unroll
        for (int mb = 0; mb < 4; mb++) {
            float m0 = -CUDART_INF_F, m1 = -CUDART_INF_F;
#pragma unroll
            for (int nb = 0; nb < 4; nb++) {
                m0 = fmaxf(m0, fmaxf(acc[mb][nb][0], acc[mb][nb][1]));
                m1 = fmaxf(m1, fmaxf(acc[mb][nb][2], acc[mb][nb][3]));
            }
            m0 = fmaxf(m0, __shfl_xor_sync(0xffffffffu, m0, 1));
            m0 = fmaxf(m0, __shfl_xor_sync(0xffffffffu, m0, 2));
            m1 = fmaxf(m1, __shfl_xor_sync(0xffffffffu, m1, 1));
            m1 = fmaxf(m1, __shfl_xor_sync(0xffffffffu, m1, 2));
            if ((lane & 3) == 0) {
                int r0 = rowBase + wm * 64 + mb * 16 + (lane >> 2);
                atomicMaxF(&g_rowmax[b * Dq + r0], m0);
                atomicMaxF(&g_rowmax[b * Dq + r0 + 8], m1);
            }
        }
    }
}

// ---- softmax over tanh(rowmax/64) ------------------------------------------
__global__ __launch_bounds__(1024) void softmax_k(float* __restrict__ out) {
    const int b = blockIdx.x;
    const int t = threadIdx.x;
    __shared__ float smax[32];
    __shared__ float ssum[32];

    float v = tanhf(g_rowmax[b * Dq + t] * 0.015625f);
    float m = v;
#pragma unroll
    for (int o = 16; o > 0; o >>= 1) m = fmaxf(m, __shfl_xor_sync(0xffffffffu, m, o));
    if ((t & 31) == 0) smax[t >> 5] = m;
    __syncthreads();
    if (t < 32) {
        float x = smax[t];
#pragma unroll
        for (int o = 16; o > 0; o >>= 1) x = fmaxf(x, __shfl_xor_sync(0xffffffffu, x, o));
        smax[t] = x;
    }
    __syncthreads();
    const float M = smax[0];
    float e = expf(v - M);
    float s = e;
#pragma unroll
    for (int o = 16; o > 0; o >>= 1) s += __shfl_xor_sync(0xffffffffu, s, o);
    if ((t & 31) == 0) ssum[t >> 5] = s;
    __syncthreads();
    if (t < 32) {
        float x = ssum[t];
#pragma unroll
        for (int o = 16; o > 0; o >>= 1) x += __shfl_xor_sync(0xffffffffu, x, o);
        ssum[t] = x;
    }
    __syncthreads();
    out[b * Dq + t] = e / ssum[0];
}

// -----------------------------------------------------------------------------
extern "C" void kernel_launch(void* const* d_in, const int* in_sizes, int n_in,
                              void* d_out, int out_size) {
    const float* emb = (const float*)d_in[0];   // [B, D, N]
    const float* W   = (const float*)d_in[2];   // [D, D]
    float* out = (float*)d_out;                 // [B, N, 1]

    cudaFuncSetAttribute(fp8_gemm_k<0>, cudaFuncAttributeMaxDynamicSharedMemorySize, SMEM_TOTAL);
    cudaFuncSetAttribute(fp8_gemm_k<1>, cudaFuncAttributeMaxDynamicSharedMemorySize, SMEM_TOTAL);

    convert_W_k<<<Dq * Dq / 512, 256>>>(W);
    convert_E_k<<<dim3(32, 32, Bq), 256>>>(emb);
    init_rowmax_k<<<(Bq * Dq + 1023) / 1024, 1024>>>();

    dim3 grid(Dq / BN, Dq / BM, Bq);   // (8, 8, 16)
    fp8_gemm_k<0><<<grid, NT, SMEM_TOTAL>>>();
    fp8_gemm_k<1><<<grid, NT, SMEM_TOTAL>>>();
    softmax_k<<<Bq, 1024>>>(out);
}

// round 9
// speedup vs baseline: 6.5667x; 1.0022x over previous
#include <cuda_runtime.h>
#include <cuda_bf16.h>
#include <math_constants.h>
#include <cstdint>

#define Dq 1024
#define Bq 16
#define BM 128
#define BN 64
#define BKB 128                       // K bytes per chunk (full row)
#define NCHUNK (Dq / BKB)             // 8
#define ASTR 144                      // padded row stride (128B + 16B)
#define A_STAGE (BM * ASTR)           // 18432 B
#define B_STAGE (BN * ASTR)           //  9216 B
#define STAGE_BYTES (A_STAGE + B_STAGE)   // 27648 B
#define NSTAGE 2
#define SMEM_TOTAL (NSTAGE * STAGE_BYTES) // 55296 B
#define NT 128

// ---- scratch (__device__ globals) ------------------------------------------
__device__ uint8_t g_W8 [(size_t)Dq * Dq];            // (64*W)[d][k] e4m3
__device__ uint8_t g_ET8[(size_t)Bq * Dq * Dq];       // E^T[b][n][d] e4m3
__device__ uint8_t g_T8 [(size_t)Bq * Dq * Dq];       // 64*Tt[b][n][d] e4m3
__device__ float g_rowmax[Bq * Dq];

// ---- helpers ---------------------------------------------------------------
__device__ __forceinline__ uint32_t smem_u32(const void* p) {
    uint32_t a;
    asm("{ .reg .u64 t; cvta.to.shared.u64 t, %1; cvt.u32.u64 %0, t; }" : "=r"(a) : "l"(p));
    return a;
}
__device__ __forceinline__ void cp16(uint32_t s, const void* g) {
    asm volatile("cp.async.cg.shared.global [%0], [%1], 16;\n" :: "r"(s), "l"(g));
}
__device__ __forceinline__ void cp_commit() { asm volatile("cp.async.commit_group;\n"); }
template <int N> __device__ __forceinline__ void cp_wait() {
    asm volatile("cp.async.wait_group %0;\n" :: "n"(N));
}
__device__ __forceinline__ void ldsm4(uint32_t* r, uint32_t addr) {
    asm volatile("ldmatrix.sync.aligned.m8n8.x4.shared.b16 {%0,%1,%2,%3}, [%4];"
                 : "=r"(r[0]), "=r"(r[1]), "=r"(r[2]), "=r"(r[3]) : "r"(addr));
}
__device__ __forceinline__ void mma_e4m3(float* d, const uint32_t* a, uint32_t b0, uint32_t b1) {
    asm volatile("mma.sync.aligned.m16n8k32.row.col.f32.e4m3.e4m3.f32 "
                 "{%0,%1,%2,%3}, {%4,%5,%6,%7}, {%8,%9}, {%0,%1,%2,%3};"
                 : "+f"(d[0]), "+f"(d[1]), "+f"(d[2]), "+f"(d[3])
                 : "r"(a[0]), "r"(a[1]), "r"(a[2]), "r"(a[3]), "r"(b0), "r"(b1));
}
__device__ __forceinline__ uint16_t cvt2_e4m3(float hi, float lo) {
    uint16_t r;
    asm("cvt.rn.satfinite.e4m3x2.f32 %0, %1, %2;" : "=h"(r) : "f"(hi), "f"(lo));
    return r;
}
__device__ __forceinline__ void atomicMaxF(float* addr, float val) {
    int old = __float_as_int(*addr);
    while (__int_as_float(old) < val) {
        int assumed = old;
        old = atomicCAS((int*)addr, assumed, __float_as_int(val));
        if (old == assumed) break;
    }
}

// ---- setup kernels ---------------------------------------------------------
__global__ void init_rowmax_k() {
    int i = blockIdx.x * blockDim.x + threadIdx.x;
    if (i < Bq * Dq) g_rowmax[i] = -CUDART_INF_F;
}
__global__ void convert_W_k(const float* __restrict__ W) {
    int i = blockIdx.x * 256 + threadIdx.x;
    float2 v = ((const float2*)W)[i];
    ((uint16_t*)g_W8)[i] = cvt2_e4m3(v.y * 64.f, v.x * 64.f);
}
__global__ __launch_bounds__(256) void convert_E_k(const float* __restrict__ E) {
    __shared__ float tile[32][33];
    const int b = blockIdx.z;
    const int x0 = blockIdx.x * 32, y0 = blockIdx.y * 32;
    const float* __restrict__ Eb = E + (size_t)b * Dq * Dq;
    const int t = threadIdx.x;
#pragma unroll
    for (int i = 0; i < 4; i++) {
        int idx = t + i * 256;
        int y = idx >> 5, x = idx & 31;
        tile[y][x] = Eb[(size_t)(y0 + y) * Dq + x0 + x];
    }
    __syncthreads();
    const int n = x0 + (t >> 3);
    const int d0 = (t & 7) * 4;
    float v0 = tile[d0 + 0][t >> 3], v1 = tile[d0 + 1][t >> 3];
    float v2 = tile[d0 + 2][t >> 3], v3 = tile[d0 + 3][t >> 3];
    uint32_t packed = (uint32_t)cvt2_e4m3(v1, v0) | ((uint32_t)cvt2_e4m3(v3, v2) << 16);
    *(uint32_t*)(g_ET8 + (size_t)b * Dq * Dq + (size_t)n * Dq + y0 + d0) = packed;
}

// ---- fp8 tensor-core GEMM ---------------------------------------------------
// 128 threads, warp grid 2(M) x 2(N), warp tile 64 x 32, CTA tile 128 x 64.
// 2-stage double buffer; 4 CTAs/SM for stall decorrelation.
// MODE 0: C = ET[b] @ (64W)^T  -> g_T8 (e4m3)
// MODE 1: C = ET[b] @ T8[b]^T  -> fused rowmax
template <int MODE>
__global__ __launch_bounds__(NT, 4) void fp8_gemm_k() {
    extern __shared__ char smem[];
    const uint32_t sbase = smem_u32(smem);
    const int t = threadIdx.x, lane = t & 31, wid = t >> 5;
    const int wm = wid >> 1, wn = wid & 1;          // 2(M) x 2(N)
    const int b = blockIdx.z;
    const int rowBase = blockIdx.y * BM;
    const int colBase = blockIdx.x * BN;

    const uint8_t* __restrict__ A = g_ET8 + (size_t)b * Dq * Dq;
    const uint8_t* __restrict__ Bm =
        (MODE == 0) ? g_W8 : (g_T8 + (size_t)b * Dq * Dq);

    float acc[4][4][4];
#pragma unroll
    for (int mb = 0; mb < 4; mb++)
#pragma unroll
        for (int nb = 0; nb < 4; nb++)
#pragma unroll
            for (int r = 0; r < 4; r++) acc[mb][nb][r] = 0.f;

    // hoisted fragment smem offsets (within a stage)
    uint32_t aoff[4], boff[2];
#pragma unroll
    for (int mb = 0; mb < 4; mb++)
        aoff[mb] = (uint32_t)((wm * 64 + mb * 16 + (lane & 15)) * ASTR + (lane >> 4) * 16);
#pragma unroll
    for (int p = 0; p < 2; p++)
        boff[p] = (uint32_t)((wn * 32 + p * 16 + ((lane >> 4) << 3) + (lane & 7)) * ASTR
                             + ((lane >> 3) & 1) * 16) + A_STAGE;

    // incrementally advanced global pointers (kills per-stage IMAD chains)
    const uint8_t* gA = A + (size_t)(rowBase + (t >> 3)) * Dq + (t & 7) * 16;
    const uint8_t* gB = Bm + (size_t)(colBase + (t >> 3)) * Dq + (t & 7) * 16;
    const uint32_t sAof = (uint32_t)((t >> 3) * ASTR + (t & 7) * 16);

    auto load_stage = [&](int c) {
        const uint32_t sS = sbase + (uint32_t)((c & 1) * STAGE_BYTES);
        const size_t k0 = (size_t)c * BKB;
#pragma unroll
        for (int i = 0; i < 8; i++)                 // A: 128 rows x 8 x 16B
            cp16(sS + sAof + (uint32_t)(i * 16 * ASTR), gA + k0 + (size_t)(i * 16) * Dq);
#pragma unroll
        for (int i = 0; i < 4; i++)                 // B: 64 rows x 8 x 16B
            cp16(sS + A_STAGE + sAof + (uint32_t)(i * 16 * ASTR),
                 gB + k0 + (size_t)(i * 16) * Dq);
        cp_commit();
    };

    load_stage(0);
    load_stage(1);

    for (int c = 0; c < NCHUNK; c++) {
        if (c + 1 < NCHUNK) cp_wait<1>(); else cp_wait<0>();
        __syncthreads();

        const uint32_t stageBase = sbase + (uint32_t)((c & 1) * STAGE_BYTES);
#pragma unroll
        for (int s = 0; s < 4; s++) {               // four k32 steps per chunk
            const uint32_t k0 = s * 32;
            uint32_t af[4][4];
#pragma unroll
            for (int mb = 0; mb < 4; mb++)
                ldsm4(af[mb], stageBase + aoff[mb] + k0);
#pragma unroll
            for (int p = 0; p < 2; p++) {
                uint32_t bf[4];
                ldsm4(bf, stageBase + boff[p] + k0);
#pragma unroll
                for (int mb = 0; mb < 4; mb++) {
                    mma_e4m3(acc[mb][2 * p + 0], af[mb], bf[0], bf[1]);
                    mma_e4m3(acc[mb][2 * p + 1], af[mb], bf[2], bf[3]);
                }
            }
        }
        __syncthreads();
        if (c + 2 < NCHUNK) load_stage(c + 2);
    }

    if (MODE == 0) {
        uint8_t* __restrict__ dst = g_T8 + (size_t)b * Dq * Dq;
#pragma unroll
        for (int mb = 0; mb < 4; mb++) {
            int r0 = rowBase + wm * 64 + mb * 16 + (lane >> 2);
#pragma unroll
            for (int nb = 0; nb < 4; nb++) {
                int col = colBase + wn * 32 + nb * 8 + (lane & 3) * 2;
                *(uint16_t*)(dst + (size_t)r0 * Dq + col) =
                    cvt2_e4m3(acc[mb][nb][1], acc[mb][nb][0]);
                *(uint16_t*)(dst + (size_t)(r0 + 8) * Dq + col) =
                    cvt2_e4m3(acc[mb][nb][3], acc[mb][nb][2]);
            }
        }
    } else {
#pragma unroll
        for (int mb = 0; mb < 4; mb++) {
            float m0 = -CUDART_INF_F, m1 = -CUDART_INF_F;
#pragma unroll
            for (int nb = 0; nb < 4; nb++) {
                m0 = fmaxf(m0, fmaxf(acc[mb][nb][0], acc[mb][nb][1]));
                m1 = fmaxf(m1, fmaxf(acc[mb][nb][2], acc[mb][nb][3]));
            }
            m0 = fmaxf(m0, __shfl_xor_sync(0xffffffffu, m0, 1));
            m0 = fmaxf(m0, __shfl_xor_sync(0xffffffffu, m0, 2));
            m1 = fmaxf(m1, __shfl_xor_sync(0xffffffffu, m1, 1));
            m1 = fmaxf(m1, __shfl_xor_sync(0xffffffffu, m1, 2));
            if ((lane & 3) == 0) {
                int r0 = rowBase + wm * 64 + mb * 16 + (lane >> 2);
                atomicMaxF(&g_rowmax[b * Dq + r0], m0);
                atomicMaxF(&g_rowmax[b * Dq + r0 + 8], m1);
            }
        }
    }
}

// ---- softmax over tanh(rowmax/64) ------------------------------------------
__global__ __launch_bounds__(1024) void softmax_k(float* __restrict__ out) {
    const int b = blockIdx.x;
    const int t = threadIdx.x;
    __shared__ float smax[32];
    __shared__ float ssum[32];

    float v = tanhf(g_rowmax[b * Dq + t] * 0.015625f);
    float m = v;
#pragma unroll
    for (int o = 16; o > 0; o >>= 1) m = fmaxf(m, __shfl_xor_sync(0xffffffffu, m, o));
    if ((t & 31) == 0) smax[t >> 5] = m;
    __syncthreads();
    if (t < 32) {
        float x = smax[t];
#pragma unroll
        for (int o = 16; o > 0; o >>= 1) x = fmaxf(x, __shfl_xor_sync(0xffffffffu, x, o));
        smax[t] = x;
    }
    __syncthreads();
    const float M = smax[0];
    float e = expf(v - M);
    float s = e;
#pragma unroll
    for (int o = 16; o > 0; o >>= 1) s += __shfl_xor_sync(0xffffffffu, s, o);
    if ((t & 31) == 0) ssum[t >> 5] = s;
    __syncthreads();
    if (t < 32) {
        float x = ssum[t];
#pragma unroll
        for (int o = 16; o > 0; o >>= 1) x += __shfl_xor_sync(0xffffffffu, x, o);
        ssum[t] = x;
    }
    __syncthreads();
    out[b * Dq + t] = e / ssum[0];
}

// -----------------------------------------------------------------------------
extern "C" void kernel_launch(void* const* d_in, const int* in_sizes, int n_in,
                              void* d_out, int out_size) {
    const float* emb = (const float*)d_in[0];   // [B, D, N]
    const float* W   = (const float*)d_in[2];   // [D, D]
    float* out = (float*)d_out;                 // [B, N, 1]

    cudaFuncSetAttribute(fp8_gemm_k<0>, cudaFuncAttributeMaxDynamicSharedMemorySize, SMEM_TOTAL);
    cudaFuncSetAttribute(fp8_gemm_k<1>, cudaFuncAttributeMaxDynamicSharedMemorySize, SMEM_TOTAL);

    convert_W_k<<<Dq * Dq / 512, 256>>>(W);
    convert_E_k<<<dim3(32, 32, Bq), 256>>>(emb);
    init_rowmax_k<<<(Bq * Dq + 1023) / 1024, 1024>>>();

    dim3 grid(Dq / BN, Dq / BM, Bq);   // (16, 8, 16)
    fp8_gemm_k<0><<<grid, NT, SMEM_TOTAL>>>();
    fp8_gemm_k<1><<<grid, NT, SMEM_TOTAL>>>();
    softmax_k<<<Bq, 1024>>>(out);
}

// round 10
// speedup vs baseline: 7.2156x; 1.0988x over previous
#include <cuda_runtime.h>
#include <cuda_bf16.h>
#include <math_constants.h>
#include <cstdint>

#define Dq 1024
#define Bq 16
#define BM 64
#define BN 64
#define BKB 128                       // K bytes per chunk (full row)
#define NCHUNK (Dq / BKB)             // 8
#define ASTR 144                      // padded row stride (128B + 16B)
#define A_STAGE (BM * ASTR)           // 9216 B
#define B_STAGE (BN * ASTR)           // 9216 B
#define STAGE_BYTES (A_STAGE + B_STAGE)   // 18432 B
#define NSTAGE 2
#define SMEM_TOTAL (NSTAGE * STAGE_BYTES) // 36864 B
#define NT 128

// ---- scratch (__device__ globals) ------------------------------------------
__device__ uint8_t g_W8 [(size_t)Dq * Dq];            // (64*W)[d][k] e4m3
__device__ uint8_t g_ET8[(size_t)Bq * Dq * Dq];       // E^T[b][n][d] e4m3
__device__ uint8_t g_T8 [(size_t)Bq * Dq * Dq];       // 64*Tt[b][n][d] e4m3
__device__ float g_rowmax[Bq * Dq];

// ---- helpers ---------------------------------------------------------------
__device__ __forceinline__ uint32_t smem_u32(const void* p) {
    uint32_t a;
    asm("{ .reg .u64 t; cvta.to.shared.u64 t, %1; cvt.u32.u64 %0, t; }" : "=r"(a) : "l"(p));
    return a;
}
__device__ __forceinline__ void cp16(uint32_t s, const void* g) {
    asm volatile("cp.async.cg.shared.global [%0], [%1], 16;\n" :: "r"(s), "l"(g));
}
__device__ __forceinline__ void cp_commit() { asm volatile("cp.async.commit_group;\n"); }
template <int N> __device__ __forceinline__ void cp_wait() {
    asm volatile("cp.async.wait_group %0;\n" :: "n"(N));
}
__device__ __forceinline__ void ldsm4(uint32_t* r, uint32_t addr) {
    asm volatile("ldmatrix.sync.aligned.m8n8.x4.shared.b16 {%0,%1,%2,%3}, [%4];"
                 : "=r"(r[0]), "=r"(r[1]), "=r"(r[2]), "=r"(r[3]) : "r"(addr));
}
__device__ __forceinline__ void mma_e4m3(float* d, const uint32_t* a, uint32_t b0, uint32_t b1) {
    asm volatile("mma.sync.aligned.m16n8k32.row.col.f32.e4m3.e4m3.f32 "
                 "{%0,%1,%2,%3}, {%4,%5,%6,%7}, {%8,%9}, {%0,%1,%2,%3};"
                 : "+f"(d[0]), "+f"(d[1]), "+f"(d[2]), "+f"(d[3])
                 : "r"(a[0]), "r"(a[1]), "r"(a[2]), "r"(a[3]), "r"(b0), "r"(b1));
}
__device__ __forceinline__ uint16_t cvt2_e4m3(float hi, float lo) {
    uint16_t r;
    asm("cvt.rn.satfinite.e4m3x2.f32 %0, %1, %2;" : "=h"(r) : "f"(hi), "f"(lo));
    return r;
}
__device__ __forceinline__ void atomicMaxF(float* addr, float val) {
    int old = __float_as_int(*addr);
    while (__int_as_float(old) < val) {
        int assumed = old;
        old = atomicCAS((int*)addr, assumed, __float_as_int(val));
        if (old == assumed) break;
    }
}

// ---- setup kernels ---------------------------------------------------------
// W fp32 -> e4m3 (scaled by 64); also initializes g_rowmax (grid covers it)
__global__ void convert_W_k(const float* __restrict__ W) {
    int i = blockIdx.x * 256 + threadIdx.x;
    float2 v = ((const float2*)W)[i];
    ((uint16_t*)g_W8)[i] = cvt2_e4m3(v.y * 64.f, v.x * 64.f);
    if (i < Bq * Dq) g_rowmax[i] = -CUDART_INF_F;
}
__global__ __launch_bounds__(256) void convert_E_k(const float* __restrict__ E) {
    __shared__ float tile[32][33];
    const int b = blockIdx.z;
    const int x0 = blockIdx.x * 32, y0 = blockIdx.y * 32;
    const float* __restrict__ Eb = E + (size_t)b * Dq * Dq;
    const int t = threadIdx.x;
#pragma unroll
    for (int i = 0; i < 4; i++) {
        int idx = t + i * 256;
        int y = idx >> 5, x = idx & 31;
        tile[y][x] = Eb[(size_t)(y0 + y) * Dq + x0 + x];
    }
    __syncthreads();
    const int n = x0 + (t >> 3);
    const int d0 = (t & 7) * 4;
    float v0 = tile[d0 + 0][t >> 3], v1 = tile[d0 + 1][t >> 3];
    float v2 = tile[d0 + 2][t >> 3], v3 = tile[d0 + 3][t >> 3];
    uint32_t packed = (uint32_t)cvt2_e4m3(v1, v0) | ((uint32_t)cvt2_e4m3(v3, v2) << 16);
    *(uint32_t*)(g_ET8 + (size_t)b * Dq * Dq + (size_t)n * Dq + y0 + d0) = packed;
}

// ---- fp8 tensor-core GEMM ---------------------------------------------------
// 128 threads, warp grid 2(M) x 2(N), warp tile 32 x 32, CTA tile 64 x 64.
// 2-stage double buffer; 6 CTAs/SM (24 warps) for latency hiding.
// MODE 0: C = ET[b] @ (64W)^T  -> g_T8 (e4m3)
// MODE 1: C = ET[b] @ T8[b]^T  -> fused rowmax
template <int MODE>
__global__ __launch_bounds__(NT, 6) void fp8_gemm_k() {
    extern __shared__ char smem[];
    const uint32_t sbase = smem_u32(smem);
    const int t = threadIdx.x, lane = t & 31, wid = t >> 5;
    const int wm = wid >> 1, wn = wid & 1;          // 2(M) x 2(N)
    const int b = blockIdx.z;
    const int rowBase = blockIdx.y * BM;
    const int colBase = blockIdx.x * BN;

    const uint8_t* __restrict__ A = g_ET8 + (size_t)b * Dq * Dq;
    const uint8_t* __restrict__ Bm =
        (MODE == 0) ? g_W8 : (g_T8 + (size_t)b * Dq * Dq);

    float acc[2][4][4];
#pragma unroll
    for (int mb = 0; mb < 2; mb++)
#pragma unroll
        for (int nb = 0; nb < 4; nb++)
#pragma unroll
            for (int r = 0; r < 4; r++) acc[mb][nb][r] = 0.f;

    // hoisted fragment smem offsets (within a stage)
    uint32_t aoff[2], boff[2];
#pragma unroll
    for (int mb = 0; mb < 2; mb++)
        aoff[mb] = (uint32_t)((wm * 32 + mb * 16 + (lane & 15)) * ASTR + (lane >> 4) * 16);
#pragma unroll
    for (int p = 0; p < 2; p++)
        boff[p] = (uint32_t)((wn * 32 + p * 16 + ((lane >> 4) << 3) + (lane & 7)) * ASTR
                             + ((lane >> 3) & 1) * 16) + A_STAGE;

    // global load pointers (16B per cp16; 4 A rows + 4 B rows per thread)
    const uint8_t* gA = A + (size_t)(rowBase + (t >> 3)) * Dq + (t & 7) * 16;
    const uint8_t* gB = Bm + (size_t)(colBase + (t >> 3)) * Dq + (t & 7) * 16;
    const uint32_t sAof = (uint32_t)((t >> 3) * ASTR + (t & 7) * 16);

    auto load_stage = [&](int c) {
        const uint32_t sS = sbase + (uint32_t)((c & 1) * STAGE_BYTES);
        const size_t k0 = (size_t)c * BKB;
#pragma unroll
        for (int i = 0; i < 4; i++)                 // A: 64 rows x 8 x 16B
            cp16(sS + sAof + (uint32_t)(i * 16 * ASTR), gA + k0 + (size_t)(i * 16) * Dq);
#pragma unroll
        for (int i = 0; i < 4; i++)                 // B: 64 rows x 8 x 16B
            cp16(sS + A_STAGE + sAof + (uint32_t)(i * 16 * ASTR),
                 gB + k0 + (size_t)(i * 16) * Dq);
        cp_commit();
    };

    load_stage(0);
    load_stage(1);

    for (int c = 0; c < NCHUNK; c++) {
        if (c + 1 < NCHUNK) cp_wait<1>(); else cp_wait<0>();
        __syncthreads();

        const uint32_t stageBase = sbase + (uint32_t)((c & 1) * STAGE_BYTES);
#pragma unroll
        for (int s = 0; s < 4; s++) {               // four k32 steps per chunk
            const uint32_t k0 = s * 32;
            uint32_t af[2][4];
#pragma unroll
            for (int mb = 0; mb < 2; mb++)
                ldsm4(af[mb], stageBase + aoff[mb] + k0);
#pragma unroll
            for (int p = 0; p < 2; p++) {
                uint32_t bf[4];
                ldsm4(bf, stageBase + boff[p] + k0);
#pragma unroll
                for (int mb = 0; mb < 2; mb++) {
                    mma_e4m3(acc[mb][2 * p + 0], af[mb], bf[0], bf[1]);
                    mma_e4m3(acc[mb][2 * p + 1], af[mb], bf[2], bf[3]);
                }
            }
        }
        __syncthreads();
        if (c + 2 < NCHUNK) load_stage(c + 2);
    }

    if (MODE == 0) {
        uint8_t* __restrict__ dst = g_T8 + (size_t)b * Dq * Dq;
#pragma unroll
        for (int mb = 0; mb < 2; mb++) {
            int r0 = rowBase + wm * 32 + mb * 16 + (lane >> 2);
#pragma unroll
            for (int nb = 0; nb < 4; nb++) {
                int col = colBase + wn * 32 + nb * 8 + (lane & 3) * 2;
                *(uint16_t*)(dst + (size_t)r0 * Dq + col) =
                    cvt2_e4m3(acc[mb][nb][1], acc[mb][nb][0]);
                *(uint16_t*)(dst + (size_t)(r0 + 8) * Dq + col) =
                    cvt2_e4m3(acc[mb][nb][3], acc[mb][nb][2]);
            }
        }
    } else {
#pragma unroll
        for (int mb = 0; mb < 2; mb++) {
            float m0 = -CUDART_INF_F, m1 = -CUDART_INF_F;
#pragma unroll
            for (int nb = 0; nb < 4; nb++) {
                m0 = fmaxf(m0, fmaxf(acc[mb][nb][0], acc[mb][nb][1]));
                m1 = fmaxf(m1, fmaxf(acc[mb][nb][2], acc[mb][nb][3]));
            }
            m0 = fmaxf(m0, __shfl_xor_sync(0xffffffffu, m0, 1));
            m0 = fmaxf(m0, __shfl_xor_sync(0xffffffffu, m0, 2));
            m1 = fmaxf(m1, __shfl_xor_sync(0xffffffffu, m1, 1));
            m1 = fmaxf(m1, __shfl_xor_sync(0xffffffffu, m1, 2));
            if ((lane & 3) == 0) {
                int r0 = rowBase + wm * 32 + mb * 16 + (lane >> 2);
                atomicMaxF(&g_rowmax[b * Dq + r0], m0);
                atomicMaxF(&g_rowmax[b * Dq + r0 + 8], m1);
            }
        }
    }
}

// ---- softmax over tanh(rowmax/64) ------------------------------------------
__global__ __launch_bounds__(1024) void softmax_k(float* __restrict__ out) {
    const int b = blockIdx.x;
    const int t = threadIdx.x;
    __shared__ float smax[32];
    __shared__ float ssum[32];

    float v = tanhf(g_rowmax[b * Dq + t] * 0.015625f);
    float m = v;
#pragma unroll
    for (int o = 16; o > 0; o >>= 1) m = fmaxf(m, __shfl_xor_sync(0xffffffffu, m, o));
    if ((t & 31) == 0) smax[t >> 5] = m;
    __syncthreads();
    if (t < 32) {
        float x = smax[t];
#pragma unroll
        for (int o = 16; o > 0; o >>= 1) x = fmaxf(x, __shfl_xor_sync(0xffffffffu, x, o));
        smax[t] = x;
    }
    __syncthreads();
    const float M = smax[0];
    float e = expf(v - M);
    float s = e;
#pragma unroll
    for (int o = 16; o > 0; o >>= 1) s += __shfl_xor_sync(0xffffffffu, s, o);
    if ((t & 31) == 0) ssum[t >> 5] = s;
    __syncthreads();
    if (t < 32) {
        float x = ssum[t];
#pragma unroll
        for (int o = 16; o > 0; o >>= 1) x += __shfl_xor_sync(0xffffffffu, x, o);
        ssum[t] = x;
    }
    __syncthreads();
    out[b * Dq + t] = e / ssum[0];
}

// -----------------------------------------------------------------------------
extern "C" void kernel_launch(void* const* d_in, const int* in_sizes, int n_in,
                              void* d_out, int out_size) {
    const float* emb = (const float*)d_in[0];   // [B, D, N]
    const float* W   = (const float*)d_in[2];   // [D, D]
    float* out = (float*)d_out;                 // [B, N, 1]

    cudaFuncSetAttribute(fp8_gemm_k<0>, cudaFuncAttributeMaxDynamicSharedMemorySize, SMEM_TOTAL);
    cudaFuncSetAttribute(fp8_gemm_k<1>, cudaFuncAttributeMaxDynamicSharedMemorySize, SMEM_TOTAL);

    convert_W_k<<<Dq * Dq / 512, 256>>>(W);
    convert_E_k<<<dim3(32, 32, Bq), 256>>>(emb);

    dim3 grid(Dq / BN, Dq / BM, Bq);   // (16, 16, 16)
    fp8_gemm_k<0><<<grid, NT, SMEM_TOTAL>>>();
    fp8_gemm_k<1><<<grid, NT, SMEM_TOTAL>>>();
    softmax_k<<<Bq, 1024>>>(out);
}